// round 1
// baseline (speedup 1.0000x reference)
#include <cuda_runtime.h>

#define B_ 2
#define S_ 2048
#define H_ 1024
#define NH_ 16
#define HD_ 64
#define C_ 256
#define FF_ 4096
#define ROWS_ (B_*S_)

// ---------------- scratch (static device allocations; no cudaMalloc) -------
__device__ float g_h[ROWS_ * H_];          // LN output
__device__ float g_qkv[ROWS_ * 3 * H_];    // fused qkv
__device__ float g_attn[ROWS_ * H_];       // attention output
__device__ float g_x[ROWS_ * H_];          // residual stream
__device__ float g_q2[ROWS_ * H_];         // cross-attn q
__device__ float g_kvc[B_ * C_ * 2 * H_];  // cross-attn kv
__device__ float g_ff[ROWS_ * FF_];        // FFN hidden

// ---------------- LayerNorm: one block (256 thr) per row of H=1024 --------
__global__ void ln_kernel(const float* __restrict__ in, const float* __restrict__ gam,
                          const float* __restrict__ bet, float* __restrict__ out) {
    int row = blockIdx.x;
    int tid = threadIdx.x;
    const float4* xr = reinterpret_cast<const float4*>(in + (size_t)row * H_);
    float4 v = xr[tid];
    float s  = v.x + v.y + v.z + v.w;
    float sq = v.x*v.x + v.y*v.y + v.z*v.z + v.w*v.w;
    #pragma unroll
    for (int o = 16; o > 0; o >>= 1) {
        s  += __shfl_xor_sync(0xffffffffu, s,  o);
        sq += __shfl_xor_sync(0xffffffffu, sq, o);
    }
    __shared__ float ss[8], ssq[8];
    __shared__ float sh_mean, sh_rstd;
    if ((tid & 31) == 0) { ss[tid >> 5] = s; ssq[tid >> 5] = sq; }
    __syncthreads();
    if (tid == 0) {
        float ts = 0.f, tq = 0.f;
        #pragma unroll
        for (int i = 0; i < 8; i++) { ts += ss[i]; tq += ssq[i]; }
        float mean = ts * (1.0f / H_);
        float var  = tq * (1.0f / H_) - mean * mean;
        sh_mean = mean;
        sh_rstd = rsqrtf(var + 1e-5f);
    }
    __syncthreads();
    float mean = sh_mean, rstd = sh_rstd;
    float4 gv = reinterpret_cast<const float4*>(gam)[tid];
    float4 bv = reinterpret_cast<const float4*>(bet)[tid];
    float4 o;
    o.x = (v.x - mean) * rstd * gv.x + bv.x;
    o.y = (v.y - mean) * rstd * gv.y + bv.y;
    o.z = (v.z - mean) * rstd * gv.z + bv.z;
    o.w = (v.w - mean) * rstd * gv.w + bv.w;
    reinterpret_cast<float4*>(out + (size_t)row * H_)[tid] = o;
}

// ---------------- RoPE applied in-place to q,k parts of g_qkv -------------
__global__ void rope_kernel(float* __restrict__ qkv, const float* __restrict__ freqs) {
    int row = blockIdx.x;            // b*S + s
    int s   = row & (S_ - 1);
    float* base = qkv + (size_t)row * (3 * H_);
    int tid = threadIdx.x;           // 256
    #pragma unroll
    for (int part = 0; part < 2; part++) {       // 0=q, 1=k
        #pragma unroll
        for (int it = 0; it < 2; it++) {
            int j = tid + it * 256;              // 0..511 => (head, d<32)
            int h = j >> 5, d = j & 31;
            float f = freqs[s * 32 + d];
            float sn, c;
            sincosf(f, &sn, &c);
            float* p = base + part * H_ + h * HD_ + d;
            float x1 = p[0], x2 = p[32];
            p[0]  = x1 * c - x2 * sn;
            p[32] = x2 * c + x1 * sn;
        }
    }
}

// ---------------- SGEMM: C[M,N] = A[M,K] @ W[K,N] (+epilogue) -------------
// 128x128x8 tile, 256 threads, 8x8 microtile per thread.
#define EPI_NONE 0
#define EPI_BIAS_RES 1
#define EPI_GELU 2

template<int EPI>
__global__ __launch_bounds__(256) void sgemm_kernel(
    const float* __restrict__ A, const float* __restrict__ W,
    const float* __restrict__ bias, const float* __restrict__ res,
    float* __restrict__ C, int M, int N, int K)
{
    __shared__ float As[8][132];   // transposed A tile, padded: conflict-free
    __shared__ float Bs[8][128];
    int tid = threadIdx.x;
    int tx = tid & 15, ty = tid >> 4;
    int bm = blockIdx.y << 7, bn = blockIdx.x << 7;

    float acc[8][8];
    #pragma unroll
    for (int i = 0; i < 8; i++)
        #pragma unroll
        for (int j = 0; j < 8; j++) acc[i][j] = 0.f;

    int arow = tid >> 1, ak = (tid & 1) << 2;
    int brow = tid >> 5, bcol = (tid & 31) << 2;
    const float* Ap = A + (size_t)(bm + arow) * K + ak;
    const float* Wp = W + (size_t)brow * N + bn + bcol;

    int nk = K >> 3;
    for (int kt = 0; kt < nk; kt++) {
        float4 av = *reinterpret_cast<const float4*>(Ap);
        float4 bv = *reinterpret_cast<const float4*>(Wp);
        As[ak + 0][arow] = av.x;
        As[ak + 1][arow] = av.y;
        As[ak + 2][arow] = av.z;
        As[ak + 3][arow] = av.w;
        *reinterpret_cast<float4*>(&Bs[brow][bcol]) = bv;
        __syncthreads();
        #pragma unroll
        for (int kk = 0; kk < 8; kk++) {
            float4 a0 = *reinterpret_cast<const float4*>(&As[kk][ty << 3]);
            float4 a1 = *reinterpret_cast<const float4*>(&As[kk][(ty << 3) + 4]);
            float4 b0 = *reinterpret_cast<const float4*>(&Bs[kk][tx << 3]);
            float4 b1 = *reinterpret_cast<const float4*>(&Bs[kk][(tx << 3) + 4]);
            float a[8] = {a0.x, a0.y, a0.z, a0.w, a1.x, a1.y, a1.z, a1.w};
            float b[8] = {b0.x, b0.y, b0.z, b0.w, b1.x, b1.y, b1.z, b1.w};
            #pragma unroll
            for (int i = 0; i < 8; i++)
                #pragma unroll
                for (int j = 0; j < 8; j++)
                    acc[i][j] += a[i] * b[j];
        }
        __syncthreads();
        Ap += 8;
        Wp += (size_t)8 * N;
    }

    #pragma unroll
    for (int i = 0; i < 8; i++) {
        int row = bm + (ty << 3) + i;
        #pragma unroll
        for (int j4 = 0; j4 < 2; j4++) {
            int col = bn + (tx << 3) + j4 * 4;
            float4 o;
            float* op = &o.x;
            #pragma unroll
            for (int u = 0; u < 4; u++) {
                float v = acc[i][j4 * 4 + u];
                if (EPI == EPI_BIAS_RES) {
                    v += bias[col + u];
                    v += res[(size_t)row * N + col + u];
                } else if (EPI == EPI_GELU) {
                    v += bias[col + u];
                    v = 0.5f * v * (1.0f + erff(v * 0.70710678118654752f));
                }
                op[u] = v;
            }
            *reinterpret_cast<float4*>(&C[(size_t)row * N + col]) = o;
        }
    }
}

// ---------------- Flash attention (64 q-rows per block, HD=64) ------------
// smem layout (floats): Qs[64][64] | Ks[64][65] | Vs[64][68] | Ps[64][68]
#define QS_LD 64
#define KS_LD 65
#define VS_LD 68
#define PS_LD 68
#define Q_OFF 0
#define K_OFF (64 * QS_LD)
#define V_OFF (K_OFF + 64 * KS_LD)
#define P_OFF (V_OFF + 64 * VS_LD)
#define ATTN_SMEM_BYTES ((P_OFF + 64 * PS_LD) * 4)

template<bool CAUSAL>
__global__ __launch_bounds__(256) void attn_kernel(
    const float* __restrict__ Qp, int q_stride,
    const float* __restrict__ Kp, const float* __restrict__ Vp, int kv_stride,
    int kv_len, const float* __restrict__ maskp,   // [B, kv_len] or null
    float* __restrict__ Op)
{
    extern __shared__ float sm[];
    float* Qs = sm + Q_OFF;
    float* Ks = sm + K_OFF;
    float* Vs = sm + V_OFF;
    float* Ps = sm + P_OFF;

    int tid = threadIdx.x;
    int tx = tid & 15, ty = tid >> 4;
    int q0 = blockIdx.x * 64;
    int h  = blockIdx.y;
    int b  = blockIdx.z;

    int lc4 = (tid & 15) * 4;
    int lr  = tid >> 4;

    // load Q tile [64 x 64]
    #pragma unroll
    for (int p = 0; p < 4; p++) {
        int r = lr + p * 16;
        float4 v = *reinterpret_cast<const float4*>(
            Qp + (size_t)(b * S_ + q0 + r) * q_stride + h * HD_ + lc4);
        Qs[r * QS_LD + lc4 + 0] = v.x;
        Qs[r * QS_LD + lc4 + 1] = v.y;
        Qs[r * QS_LD + lc4 + 2] = v.z;
        Qs[r * QS_LD + lc4 + 3] = v.w;
    }

    float acc[4][4];
    float m_i[4], l_i[4];
    #pragma unroll
    for (int i = 0; i < 4; i++) {
        m_i[i] = -1e30f; l_i[i] = 0.f;
        #pragma unroll
        for (int j = 0; j < 4; j++) acc[i][j] = 0.f;
    }

    int ktiles = CAUSAL ? (q0 / 64 + 1) : (kv_len / 64);
    const float* mrow = maskp ? (maskp + (size_t)b * kv_len) : nullptr;

    for (int kt = 0; kt < ktiles; kt++) {
        int k0 = kt * 64;
        __syncthreads();  // prev-iter reads of Ks/Vs/Ps done; Qs visible on iter 0
        #pragma unroll
        for (int p = 0; p < 4; p++) {
            int r = lr + p * 16;
            size_t off = (size_t)(b * kv_len + k0 + r) * kv_stride + h * HD_ + lc4;
            float4 kv4 = *reinterpret_cast<const float4*>(Kp + off);
            Ks[r * KS_LD + lc4 + 0] = kv4.x;
            Ks[r * KS_LD + lc4 + 1] = kv4.y;
            Ks[r * KS_LD + lc4 + 2] = kv4.z;
            Ks[r * KS_LD + lc4 + 3] = kv4.w;
            float4 vv4 = *reinterpret_cast<const float4*>(Vp + off);
            *reinterpret_cast<float4*>(&Vs[r * VS_LD + lc4]) = vv4;
        }
        __syncthreads();

        // scores S[4q][4k]
        float s[4][4];
        #pragma unroll
        for (int i = 0; i < 4; i++)
            #pragma unroll
            for (int j = 0; j < 4; j++) s[i][j] = 0.f;
        #pragma unroll 16
        for (int d = 0; d < 64; d++) {
            float q[4], k[4];
            #pragma unroll
            for (int i = 0; i < 4; i++) q[i] = Qs[(ty * 4 + i) * QS_LD + d];
            #pragma unroll
            for (int j = 0; j < 4; j++) k[j] = Ks[(tx * 4 + j) * KS_LD + d];
            #pragma unroll
            for (int i = 0; i < 4; i++)
                #pragma unroll
                for (int j = 0; j < 4; j++) s[i][j] += q[i] * k[j];
        }
        float mv[4] = {0.f, 0.f, 0.f, 0.f};
        if (mrow) {
            #pragma unroll
            for (int j = 0; j < 4; j++) mv[j] = mrow[k0 + tx * 4 + j];
        }
        #pragma unroll
        for (int i = 0; i < 4; i++)
            #pragma unroll
            for (int j = 0; j < 4; j++) {
                s[i][j] = s[i][j] * 0.125f + mv[j];
                if (CAUSAL && kt == q0 / 64) {
                    if (k0 + tx * 4 + j > q0 + ty * 4 + i) s[i][j] = -1e30f;
                }
            }

        // online softmax update (per q-row stats shared across the 16-lane tx group)
        #pragma unroll
        for (int i = 0; i < 4; i++) {
            float mt = fmaxf(fmaxf(s[i][0], s[i][1]), fmaxf(s[i][2], s[i][3]));
            #pragma unroll
            for (int o = 8; o > 0; o >>= 1)
                mt = fmaxf(mt, __shfl_xor_sync(0xffffffffu, mt, o));
            float mn = fmaxf(m_i[i], mt);
            float alpha = __expf(m_i[i] - mn);
            m_i[i] = mn;
            float sum = 0.f;
            #pragma unroll
            for (int j = 0; j < 4; j++) {
                float pv = __expf(s[i][j] - mn);
                Ps[(ty * 4 + i) * PS_LD + tx * 4 + j] = pv;
                sum += pv;
            }
            #pragma unroll
            for (int o = 8; o > 0; o >>= 1)
                sum += __shfl_xor_sync(0xffffffffu, sum, o);
            l_i[i] = l_i[i] * alpha + sum;
            #pragma unroll
            for (int j = 0; j < 4; j++) acc[i][j] *= alpha;
        }
        __syncthreads();

        // O += P @ V   (tx now indexes d-columns)
        #pragma unroll 8
        for (int c = 0; c < 64; c++) {
            float4 v4 = *reinterpret_cast<const float4*>(&Vs[c * VS_LD + tx * 4]);
            #pragma unroll
            for (int i = 0; i < 4; i++) {
                float pv = Ps[(ty * 4 + i) * PS_LD + c];
                acc[i][0] += pv * v4.x;
                acc[i][1] += pv * v4.y;
                acc[i][2] += pv * v4.z;
                acc[i][3] += pv * v4.w;
            }
        }
    }

    #pragma unroll
    for (int i = 0; i < 4; i++) {
        int q = q0 + ty * 4 + i;
        float inv = 1.0f / l_i[i];
        float4 o = make_float4(acc[i][0] * inv, acc[i][1] * inv,
                               acc[i][2] * inv, acc[i][3] * inv);
        *reinterpret_cast<float4*>(
            Op + (size_t)(b * S_ + q) * H_ + h * HD_ + tx * 4) = o;
    }
}

// ---------------- launch ---------------------------------------------------
extern "C" void kernel_launch(void* const* d_in, const int* in_sizes, int n_in,
                              void* d_out, int out_size) {
    const float* x      = (const float*)d_in[0];
    const float* rope   = (const float*)d_in[1];
    // d_in[2] attention_mask: exactly tril/-1e9 causal — handled structurally
    const float* cond   = (const float*)d_in[3];
    const float* cmask  = (const float*)d_in[4];
    const float* ln1_g  = (const float*)d_in[5];
    const float* ln1_b  = (const float*)d_in[6];
    const float* ln2_g  = (const float*)d_in[7];
    const float* ln2_b  = (const float*)d_in[8];
    const float* lnc_g  = (const float*)d_in[9];
    const float* lnc_b  = (const float*)d_in[10];
    const float* w_qkv  = (const float*)d_in[11];
    const float* w_out  = (const float*)d_in[12];
    const float* b_out  = (const float*)d_in[13];
    const float* w_cq   = (const float*)d_in[14];
    const float* w_ckv  = (const float*)d_in[15];
    const float* w_cout = (const float*)d_in[16];
    const float* b_cout = (const float*)d_in[17];
    const float* w_ff1  = (const float*)d_in[18];
    const float* b_ff1  = (const float*)d_in[19];
    const float* w_ff2  = (const float*)d_in[20];
    const float* b_ff2  = (const float*)d_in[21];
    float* out = (float*)d_out;

    float *h, *qkv, *attn, *xb, *q2, *kvc, *ff;
    cudaGetSymbolAddress((void**)&h,    g_h);
    cudaGetSymbolAddress((void**)&qkv,  g_qkv);
    cudaGetSymbolAddress((void**)&attn, g_attn);
    cudaGetSymbolAddress((void**)&xb,   g_x);
    cudaGetSymbolAddress((void**)&q2,   g_q2);
    cudaGetSymbolAddress((void**)&kvc,  g_kvc);
    cudaGetSymbolAddress((void**)&ff,   g_ff);

    cudaFuncSetAttribute(attn_kernel<true>,  cudaFuncAttributeMaxDynamicSharedMemorySize, ATTN_SMEM_BYTES);
    cudaFuncSetAttribute(attn_kernel<false>, cudaFuncAttributeMaxDynamicSharedMemorySize, ATTN_SMEM_BYTES);

    const int rows = ROWS_;  // 4096

    // --- self attention ---
    ln_kernel<<<rows, 256>>>(x, ln1_g, ln1_b, h);
    sgemm_kernel<EPI_NONE><<<dim3(3 * H_ / 128, rows / 128), 256>>>(
        h, w_qkv, nullptr, nullptr, qkv, rows, 3 * H_, H_);
    rope_kernel<<<rows, 256>>>(qkv, rope);
    attn_kernel<true><<<dim3(S_ / 64, NH_, B_), 256, ATTN_SMEM_BYTES>>>(
        qkv, 3 * H_, qkv + H_, qkv + 2 * H_, 3 * H_, S_, nullptr, attn);
    sgemm_kernel<EPI_BIAS_RES><<<dim3(H_ / 128, rows / 128), 256>>>(
        attn, w_out, b_out, x, xb, rows, H_, H_);

    // --- cross attention ---
    ln_kernel<<<rows, 256>>>(xb, lnc_g, lnc_b, h);
    sgemm_kernel<EPI_NONE><<<dim3(H_ / 128, rows / 128), 256>>>(
        h, w_cq, nullptr, nullptr, q2, rows, H_, H_);
    sgemm_kernel<EPI_NONE><<<dim3(2 * H_ / 128, (B_ * C_) / 128), 256>>>(
        cond, w_ckv, nullptr, nullptr, kvc, B_ * C_, 2 * H_, H_);
    attn_kernel<false><<<dim3(S_ / 64, NH_, B_), 256, ATTN_SMEM_BYTES>>>(
        q2, H_, kvc, kvc + H_, 2 * H_, C_, cmask, attn);
    sgemm_kernel<EPI_BIAS_RES><<<dim3(H_ / 128, rows / 128), 256>>>(
        attn, w_cout, b_cout, xb, xb, rows, H_, H_);

    // --- FFN ---
    ln_kernel<<<rows, 256>>>(xb, ln2_g, ln2_b, h);
    sgemm_kernel<EPI_GELU><<<dim3(FF_ / 128, rows / 128), 256>>>(
        h, w_ff1, b_ff1, nullptr, ff, rows, FF_, H_);
    sgemm_kernel<EPI_BIAS_RES><<<dim3(H_ / 128, rows / 128), 256>>>(
        ff, w_ff2, b_ff2, xb, out, rows, H_, FF_);
}

// round 2
// speedup vs baseline: 2.0485x; 2.0485x over previous
#include <cuda_runtime.h>
#include <cstdint>

#define B_ 2
#define S_ 2048
#define H_ 1024
#define NH_ 16
#define HD_ 64
#define C_ 256
#define FF_ 4096
#define ROWS_ (B_*S_)

// ---------------- scratch (static device allocations; no cudaMalloc) -------
__device__ float g_h[ROWS_ * H_];          // LN output
__device__ float g_qkv[ROWS_ * 3 * H_];    // fused qkv
__device__ float g_attn[ROWS_ * H_];       // attention output
__device__ float g_x[ROWS_ * H_];          // residual stream
__device__ float g_q2[ROWS_ * H_];         // cross-attn q
__device__ float g_kvc[B_ * C_ * 2 * H_];  // cross-attn kv
__device__ float g_ff[ROWS_ * FF_];        // FFN hidden

// ---------------- LayerNorm: one block (256 thr) per row of H=1024 --------
__global__ void ln_kernel(const float* __restrict__ in, const float* __restrict__ gam,
                          const float* __restrict__ bet, float* __restrict__ out) {
    int row = blockIdx.x;
    int tid = threadIdx.x;
    const float4* xr = reinterpret_cast<const float4*>(in + (size_t)row * H_);
    float4 v = xr[tid];
    float s  = v.x + v.y + v.z + v.w;
    float sq = v.x*v.x + v.y*v.y + v.z*v.z + v.w*v.w;
    #pragma unroll
    for (int o = 16; o > 0; o >>= 1) {
        s  += __shfl_xor_sync(0xffffffffu, s,  o);
        sq += __shfl_xor_sync(0xffffffffu, sq, o);
    }
    __shared__ float ss[8], ssq[8];
    __shared__ float sh_mean, sh_rstd;
    if ((tid & 31) == 0) { ss[tid >> 5] = s; ssq[tid >> 5] = sq; }
    __syncthreads();
    if (tid == 0) {
        float ts = 0.f, tq = 0.f;
        #pragma unroll
        for (int i = 0; i < 8; i++) { ts += ss[i]; tq += ssq[i]; }
        float mean = ts * (1.0f / H_);
        float var  = tq * (1.0f / H_) - mean * mean;
        sh_mean = mean;
        sh_rstd = rsqrtf(var + 1e-5f);
    }
    __syncthreads();
    float mean = sh_mean, rstd = sh_rstd;
    float4 gv = reinterpret_cast<const float4*>(gam)[tid];
    float4 bv = reinterpret_cast<const float4*>(bet)[tid];
    float4 o;
    o.x = (v.x - mean) * rstd * gv.x + bv.x;
    o.y = (v.y - mean) * rstd * gv.y + bv.y;
    o.z = (v.z - mean) * rstd * gv.z + bv.z;
    o.w = (v.w - mean) * rstd * gv.w + bv.w;
    reinterpret_cast<float4*>(out + (size_t)row * H_)[tid] = o;
}

// ---------------- RoPE applied in-place to q,k parts of g_qkv -------------
__global__ void rope_kernel(float* __restrict__ qkv, const float* __restrict__ freqs) {
    int row = blockIdx.x;            // b*S + s
    int s   = row & (S_ - 1);
    float* base = qkv + (size_t)row * (3 * H_);
    int tid = threadIdx.x;           // 256
    #pragma unroll
    for (int part = 0; part < 2; part++) {       // 0=q, 1=k
        #pragma unroll
        for (int it = 0; it < 2; it++) {
            int j = tid + it * 256;              // 0..511 => (head, d<32)
            int h = j >> 5, d = j & 31;
            float f = freqs[s * 32 + d];
            float sn, c;
            sincosf(f, &sn, &c);
            float* p = base + part * H_ + h * HD_ + d;
            float x1 = p[0], x2 = p[32];
            p[0]  = x1 * c - x2 * sn;
            p[32] = x2 * c + x1 * sn;
        }
    }
}

// ---------------- TF32 tensor-core GEMM ------------------------------------
// C[M,N] = A[M,K] @ W[K,N] (+epilogue).
// Block tile 128x128, K-chunk 32, 8 warps each computing 32(M)x64(N)
// via mma.sync.m16n8k8.tf32. A in smem row-major [128][32] pad 36.
// W transposed into smem Bt[n][k] [128][32] pad 36 so both operands
// feed ldmatrix.x4 (tf32 fragments == b16 ldmatrix layout as b32).
#define EPI_NONE 0
#define EPI_BIAS_RES 1
#define EPI_GELU 2

__device__ __forceinline__ uint32_t f2tf32(float x) {
    uint32_t y;
    asm("cvt.rna.tf32.f32 %0, %1;" : "=r"(y) : "f"(x));
    return y;
}
__device__ __forceinline__ void ldsm_x4(uint32_t addr, uint32_t& r0, uint32_t& r1,
                                        uint32_t& r2, uint32_t& r3) {
    asm volatile("ldmatrix.sync.aligned.m8n8.x4.shared.b16 {%0,%1,%2,%3}, [%4];"
                 : "=r"(r0), "=r"(r1), "=r"(r2), "=r"(r3) : "r"(addr));
}
__device__ __forceinline__ void mma_tf32(float& c0, float& c1, float& c2, float& c3,
                                         uint32_t a0, uint32_t a1, uint32_t a2, uint32_t a3,
                                         uint32_t b0, uint32_t b1) {
    asm volatile("mma.sync.aligned.m16n8k8.row.col.f32.tf32.tf32.f32 "
                 "{%0,%1,%2,%3},{%4,%5,%6,%7},{%8,%9},{%0,%1,%2,%3};"
                 : "+f"(c0), "+f"(c1), "+f"(c2), "+f"(c3)
                 : "r"(a0), "r"(a1), "r"(a2), "r"(a3), "r"(b0), "r"(b1));
}

#define TG_PAD 36

template<int EPI>
__global__ __launch_bounds__(256) void tgemm_kernel(
    const float* __restrict__ A, const float* __restrict__ W,
    const float* __restrict__ bias, const float* __restrict__ res,
    float* __restrict__ C, int M, int N, int K)
{
    __shared__ uint32_t As[128 * TG_PAD];
    __shared__ uint32_t Bt[128 * TG_PAD];

    int tid  = threadIdx.x;
    int lane = tid & 31, w = tid >> 5;
    int wm = (w & 3) * 32;       // warp M offset in tile
    int wn = (w >> 2) * 64;      // warp N offset in tile
    int bm = blockIdx.y << 7, bn = blockIdx.x << 7;

    float acc[2][8][4];
    #pragma unroll
    for (int mt = 0; mt < 2; mt++)
        #pragma unroll
        for (int nt = 0; nt < 8; nt++)
            #pragma unroll
            for (int u = 0; u < 4; u++) acc[mt][nt][u] = 0.f;

    // A-load mapping: 2 threads per row, each covers 16 floats (4x float4)
    int arow = tid >> 1, ac0 = (tid & 1) * 16;
    // W-load mapping: 8 threads per k-row, 4 passes over n
    int krow = tid >> 3, nc0 = (tid & 7) * 4;

    const float* Ap = A + (size_t)(bm + arow) * K + ac0;
    const float* Wp = W + (size_t)krow * N + bn + nc0;

    // ldmatrix per-lane smem addresses (byte offsets computed once)
    int g = lane >> 3, lr = lane & 7;
    uint32_t as_base = (uint32_t)__cvta_generic_to_shared(As);
    uint32_t bt_base = (uint32_t)__cvta_generic_to_shared(Bt);
    // A tile (m16k8): matrices {rows0-7 kc0, rows8-15 kc0, rows0-7 kc1, rows8-15 kc1}
    uint32_t a_off = as_base + ((wm + (g & 1) * 8 + lr) * TG_PAD + (g >> 1) * 4) * 4;
    // B pair tile (2 x n8, k8): {n0-7 kc0, n0-7 kc1, n8-15 kc0, n8-15 kc1}
    uint32_t b_off = bt_base + ((wn + (g >> 1) * 8 + lr) * TG_PAD + (g & 1) * 4) * 4;

    int nkt = K >> 5;
    for (int kt = 0; kt < nkt; kt++) {
        // --- stage A tile [128 x 32] ---
        #pragma unroll
        for (int i = 0; i < 4; i++) {
            float4 v = *reinterpret_cast<const float4*>(Ap + i * 4);
            uint32_t* d = &As[arow * TG_PAD + ac0 + i * 4];
            d[0] = f2tf32(v.x); d[1] = f2tf32(v.y);
            d[2] = f2tf32(v.z); d[3] = f2tf32(v.w);
        }
        // --- stage W tile [32 x 128] transposed into Bt[n][k] ---
        #pragma unroll
        for (int i = 0; i < 4; i++) {
            float4 v = *reinterpret_cast<const float4*>(Wp + i * 32);
            int n = nc0 + i * 32;
            Bt[(n + 0) * TG_PAD + krow] = f2tf32(v.x);
            Bt[(n + 1) * TG_PAD + krow] = f2tf32(v.y);
            Bt[(n + 2) * TG_PAD + krow] = f2tf32(v.z);
            Bt[(n + 3) * TG_PAD + krow] = f2tf32(v.w);
        }
        __syncthreads();

        #pragma unroll
        for (int k8 = 0; k8 < 4; k8++) {
            uint32_t a[2][4];
            #pragma unroll
            for (int mt = 0; mt < 2; mt++)
                ldsm_x4(a_off + (mt * 16 * TG_PAD + k8 * 8) * 4,
                        a[mt][0], a[mt][1], a[mt][2], a[mt][3]);
            uint32_t b[8][2];
            #pragma unroll
            for (int np = 0; np < 4; np++) {
                uint32_t r0, r1, r2, r3;
                ldsm_x4(b_off + (np * 16 * TG_PAD + k8 * 8) * 4, r0, r1, r2, r3);
                b[np * 2 + 0][0] = r0; b[np * 2 + 0][1] = r1;
                b[np * 2 + 1][0] = r2; b[np * 2 + 1][1] = r3;
            }
            #pragma unroll
            for (int mt = 0; mt < 2; mt++)
                #pragma unroll
                for (int nt = 0; nt < 8; nt++)
                    mma_tf32(acc[mt][nt][0], acc[mt][nt][1], acc[mt][nt][2], acc[mt][nt][3],
                             a[mt][0], a[mt][1], a[mt][2], a[mt][3],
                             b[nt][0], b[nt][1]);
        }
        __syncthreads();
        Ap += 32;
        Wp += (size_t)32 * N;
    }

    // --- epilogue: c0,c1 at (row, col..col+1); c2,c3 at (row+8) ---
    int rbase = bm + wm + (lane >> 2);
    int cbase = bn + wn + (lane & 3) * 2;
    #pragma unroll
    for (int mt = 0; mt < 2; mt++) {
        #pragma unroll
        for (int half = 0; half < 2; half++) {
            int row = rbase + mt * 16 + half * 8;
            #pragma unroll
            for (int nt = 0; nt < 8; nt++) {
                int col = cbase + nt * 8;
                float v0 = acc[mt][nt][half * 2 + 0];
                float v1 = acc[mt][nt][half * 2 + 1];
                if (EPI == EPI_BIAS_RES) {
                    v0 += bias[col]     + res[(size_t)row * N + col];
                    v1 += bias[col + 1] + res[(size_t)row * N + col + 1];
                } else if (EPI == EPI_GELU) {
                    v0 += bias[col];
                    v1 += bias[col + 1];
                    v0 = 0.5f * v0 * (1.0f + erff(v0 * 0.70710678118654752f));
                    v1 = 0.5f * v1 * (1.0f + erff(v1 * 0.70710678118654752f));
                }
                *reinterpret_cast<float2*>(&C[(size_t)row * N + col]) = make_float2(v0, v1);
            }
        }
    }
}

// ---------------- Flash attention (64 q-rows per block, HD=64) ------------
#define QS_LD 64
#define KS_LD 65
#define VS_LD 68
#define PS_LD 68
#define Q_OFF 0
#define K_OFF (64 * QS_LD)
#define V_OFF (K_OFF + 64 * KS_LD)
#define P_OFF (V_OFF + 64 * VS_LD)
#define ATTN_SMEM_BYTES ((P_OFF + 64 * PS_LD) * 4)

template<bool CAUSAL>
__global__ __launch_bounds__(256) void attn_kernel(
    const float* __restrict__ Qp, int q_stride,
    const float* __restrict__ Kp, const float* __restrict__ Vp, int kv_stride,
    int kv_len, const float* __restrict__ maskp,   // [B, kv_len] or null
    float* __restrict__ Op)
{
    extern __shared__ float sm[];
    float* Qs = sm + Q_OFF;
    float* Ks = sm + K_OFF;
    float* Vs = sm + V_OFF;
    float* Ps = sm + P_OFF;

    int tid = threadIdx.x;
    int tx = tid & 15, ty = tid >> 4;
    int q0 = blockIdx.x * 64;
    int h  = blockIdx.y;
    int b  = blockIdx.z;

    int lc4 = (tid & 15) * 4;
    int lr  = tid >> 4;

    #pragma unroll
    for (int p = 0; p < 4; p++) {
        int r = lr + p * 16;
        float4 v = *reinterpret_cast<const float4*>(
            Qp + (size_t)(b * S_ + q0 + r) * q_stride + h * HD_ + lc4);
        Qs[r * QS_LD + lc4 + 0] = v.x;
        Qs[r * QS_LD + lc4 + 1] = v.y;
        Qs[r * QS_LD + lc4 + 2] = v.z;
        Qs[r * QS_LD + lc4 + 3] = v.w;
    }

    float acc[4][4];
    float m_i[4], l_i[4];
    #pragma unroll
    for (int i = 0; i < 4; i++) {
        m_i[i] = -1e30f; l_i[i] = 0.f;
        #pragma unroll
        for (int j = 0; j < 4; j++) acc[i][j] = 0.f;
    }

    int ktiles = CAUSAL ? (q0 / 64 + 1) : (kv_len / 64);
    const float* mrow = maskp ? (maskp + (size_t)b * kv_len) : nullptr;

    for (int kt = 0; kt < ktiles; kt++) {
        int k0 = kt * 64;
        __syncthreads();
        #pragma unroll
        for (int p = 0; p < 4; p++) {
            int r = lr + p * 16;
            size_t off = (size_t)(b * kv_len + k0 + r) * kv_stride + h * HD_ + lc4;
            float4 kv4 = *reinterpret_cast<const float4*>(Kp + off);
            Ks[r * KS_LD + lc4 + 0] = kv4.x;
            Ks[r * KS_LD + lc4 + 1] = kv4.y;
            Ks[r * KS_LD + lc4 + 2] = kv4.z;
            Ks[r * KS_LD + lc4 + 3] = kv4.w;
            float4 vv4 = *reinterpret_cast<const float4*>(Vp + off);
            *reinterpret_cast<float4*>(&Vs[r * VS_LD + lc4]) = vv4;
        }
        __syncthreads();

        float s[4][4];
        #pragma unroll
        for (int i = 0; i < 4; i++)
            #pragma unroll
            for (int j = 0; j < 4; j++) s[i][j] = 0.f;
        #pragma unroll 16
        for (int d = 0; d < 64; d++) {
            float q[4], k[4];
            #pragma unroll
            for (int i = 0; i < 4; i++) q[i] = Qs[(ty * 4 + i) * QS_LD + d];
            #pragma unroll
            for (int j = 0; j < 4; j++) k[j] = Ks[(tx * 4 + j) * KS_LD + d];
            #pragma unroll
            for (int i = 0; i < 4; i++)
                #pragma unroll
                for (int j = 0; j < 4; j++) s[i][j] += q[i] * k[j];
        }
        float mv[4] = {0.f, 0.f, 0.f, 0.f};
        if (mrow) {
            #pragma unroll
            for (int j = 0; j < 4; j++) mv[j] = mrow[k0 + tx * 4 + j];
        }
        #pragma unroll
        for (int i = 0; i < 4; i++)
            #pragma unroll
            for (int j = 0; j < 4; j++) {
                s[i][j] = s[i][j] * 0.125f + mv[j];
                if (CAUSAL && kt == q0 / 64) {
                    if (k0 + tx * 4 + j > q0 + ty * 4 + i) s[i][j] = -1e30f;
                }
            }

        #pragma unroll
        for (int i = 0; i < 4; i++) {
            float mt = fmaxf(fmaxf(s[i][0], s[i][1]), fmaxf(s[i][2], s[i][3]));
            #pragma unroll
            for (int o = 8; o > 0; o >>= 1)
                mt = fmaxf(mt, __shfl_xor_sync(0xffffffffu, mt, o));
            float mn = fmaxf(m_i[i], mt);
            float alpha = __expf(m_i[i] - mn);
            m_i[i] = mn;
            float sum = 0.f;
            #pragma unroll
            for (int j = 0; j < 4; j++) {
                float pv = __expf(s[i][j] - mn);
                Ps[(ty * 4 + i) * PS_LD + tx * 4 + j] = pv;
                sum += pv;
            }
            #pragma unroll
            for (int o = 8; o > 0; o >>= 1)
                sum += __shfl_xor_sync(0xffffffffu, sum, o);
            l_i[i] = l_i[i] * alpha + sum;
            #pragma unroll
            for (int j = 0; j < 4; j++) acc[i][j] *= alpha;
        }
        __syncthreads();

        #pragma unroll 8
        for (int c = 0; c < 64; c++) {
            float4 v4 = *reinterpret_cast<const float4*>(&Vs[c * VS_LD + tx * 4]);
            #pragma unroll
            for (int i = 0; i < 4; i++) {
                float pv = Ps[(ty * 4 + i) * PS_LD + c];
                acc[i][0] += pv * v4.x;
                acc[i][1] += pv * v4.y;
                acc[i][2] += pv * v4.z;
                acc[i][3] += pv * v4.w;
            }
        }
    }

    #pragma unroll
    for (int i = 0; i < 4; i++) {
        int q = q0 + ty * 4 + i;
        float inv = 1.0f / l_i[i];
        float4 o = make_float4(acc[i][0] * inv, acc[i][1] * inv,
                               acc[i][2] * inv, acc[i][3] * inv);
        *reinterpret_cast<float4*>(
            Op + (size_t)(b * S_ + q) * H_ + h * HD_ + tx * 4) = o;
    }
}

// ---------------- launch ---------------------------------------------------
extern "C" void kernel_launch(void* const* d_in, const int* in_sizes, int n_in,
                              void* d_out, int out_size) {
    const float* x      = (const float*)d_in[0];
    const float* rope   = (const float*)d_in[1];
    const float* cond   = (const float*)d_in[3];
    const float* cmask  = (const float*)d_in[4];
    const float* ln1_g  = (const float*)d_in[5];
    const float* ln1_b  = (const float*)d_in[6];
    const float* ln2_g  = (const float*)d_in[7];
    const float* ln2_b  = (const float*)d_in[8];
    const float* lnc_g  = (const float*)d_in[9];
    const float* lnc_b  = (const float*)d_in[10];
    const float* w_qkv  = (const float*)d_in[11];
    const float* w_out  = (const float*)d_in[12];
    const float* b_out  = (const float*)d_in[13];
    const float* w_cq   = (const float*)d_in[14];
    const float* w_ckv  = (const float*)d_in[15];
    const float* w_cout = (const float*)d_in[16];
    const float* b_cout = (const float*)d_in[17];
    const float* w_ff1  = (const float*)d_in[18];
    const float* b_ff1  = (const float*)d_in[19];
    const float* w_ff2  = (const float*)d_in[20];
    const float* b_ff2  = (const float*)d_in[21];
    float* out = (float*)d_out;

    float *h, *qkv, *attn, *xb, *q2, *kvc, *ff;
    cudaGetSymbolAddress((void**)&h,    g_h);
    cudaGetSymbolAddress((void**)&qkv,  g_qkv);
    cudaGetSymbolAddress((void**)&attn, g_attn);
    cudaGetSymbolAddress((void**)&xb,   g_x);
    cudaGetSymbolAddress((void**)&q2,   g_q2);
    cudaGetSymbolAddress((void**)&kvc,  g_kvc);
    cudaGetSymbolAddress((void**)&ff,   g_ff);

    cudaFuncSetAttribute(attn_kernel<true>,  cudaFuncAttributeMaxDynamicSharedMemorySize, ATTN_SMEM_BYTES);
    cudaFuncSetAttribute(attn_kernel<false>, cudaFuncAttributeMaxDynamicSharedMemorySize, ATTN_SMEM_BYTES);

    const int rows = ROWS_;  // 4096

    // --- self attention ---
    ln_kernel<<<rows, 256>>>(x, ln1_g, ln1_b, h);
    tgemm_kernel<EPI_NONE><<<dim3(3 * H_ / 128, rows / 128), 256>>>(
        h, w_qkv, nullptr, nullptr, qkv, rows, 3 * H_, H_);
    rope_kernel<<<rows, 256>>>(qkv, rope);
    attn_kernel<true><<<dim3(S_ / 64, NH_, B_), 256, ATTN_SMEM_BYTES>>>(
        qkv, 3 * H_, qkv + H_, qkv + 2 * H_, 3 * H_, S_, nullptr, attn);
    tgemm_kernel<EPI_BIAS_RES><<<dim3(H_ / 128, rows / 128), 256>>>(
        attn, w_out, b_out, x, xb, rows, H_, H_);

    // --- cross attention ---
    ln_kernel<<<rows, 256>>>(xb, lnc_g, lnc_b, h);
    tgemm_kernel<EPI_NONE><<<dim3(H_ / 128, rows / 128), 256>>>(
        h, w_cq, nullptr, nullptr, q2, rows, H_, H_);
    tgemm_kernel<EPI_NONE><<<dim3(2 * H_ / 128, (B_ * C_) / 128), 256>>>(
        cond, w_ckv, nullptr, nullptr, kvc, B_ * C_, 2 * H_, H_);
    attn_kernel<false><<<dim3(S_ / 64, NH_, B_), 256, ATTN_SMEM_BYTES>>>(
        q2, H_, kvc, kvc + H_, 2 * H_, C_, cmask, attn);
    tgemm_kernel<EPI_BIAS_RES><<<dim3(H_ / 128, rows / 128), 256>>>(
        attn, w_cout, b_cout, xb, xb, rows, H_, H_);

    // --- FFN ---
    ln_kernel<<<rows, 256>>>(xb, ln2_g, ln2_b, h);
    tgemm_kernel<EPI_GELU><<<dim3(FF_ / 128, rows / 128), 256>>>(
        h, w_ff1, b_ff1, nullptr, ff, rows, FF_, H_);
    tgemm_kernel<EPI_BIAS_RES><<<dim3(H_ / 128, rows / 128), 256>>>(
        ff, w_ff2, b_ff2, xb, out, rows, H_, FF_);
}

// round 4
// speedup vs baseline: 2.5813x; 1.2600x over previous
#include <cuda_runtime.h>
#include <cstdint>

#define B_ 2
#define S_ 2048
#define H_ 1024
#define NH_ 16
#define HD_ 64
#define C_ 256
#define FF_ 4096
#define ROWS_ (B_*S_)

// ---------------- scratch (static device allocations; no cudaMalloc) -------
__device__ float g_h[ROWS_ * H_];
__device__ float g_qkv[ROWS_ * 3 * H_];
__device__ float g_attn[ROWS_ * H_];
__device__ float g_x[ROWS_ * H_];
__device__ float g_q2[ROWS_ * H_];
__device__ float g_kvc[B_ * C_ * 2 * H_];
__device__ float g_ff[ROWS_ * FF_];

// ---------------- LayerNorm ------------------------------------------------
__global__ void ln_kernel(const float* __restrict__ in, const float* __restrict__ gam,
                          const float* __restrict__ bet, float* __restrict__ out) {
    int row = blockIdx.x;
    int tid = threadIdx.x;
    const float4* xr = reinterpret_cast<const float4*>(in + (size_t)row * H_);
    float4 v = xr[tid];
    float s  = v.x + v.y + v.z + v.w;
    float sq = v.x*v.x + v.y*v.y + v.z*v.z + v.w*v.w;
    #pragma unroll
    for (int o = 16; o > 0; o >>= 1) {
        s  += __shfl_xor_sync(0xffffffffu, s,  o);
        sq += __shfl_xor_sync(0xffffffffu, sq, o);
    }
    __shared__ float ss[8], ssq[8];
    __shared__ float sh_mean, sh_rstd;
    if ((tid & 31) == 0) { ss[tid >> 5] = s; ssq[tid >> 5] = sq; }
    __syncthreads();
    if (tid == 0) {
        float ts = 0.f, tq = 0.f;
        #pragma unroll
        for (int i = 0; i < 8; i++) { ts += ss[i]; tq += ssq[i]; }
        float mean = ts * (1.0f / H_);
        float var  = tq * (1.0f / H_) - mean * mean;
        sh_mean = mean;
        sh_rstd = rsqrtf(var + 1e-5f);
    }
    __syncthreads();
    float mean = sh_mean, rstd = sh_rstd;
    float4 gv = reinterpret_cast<const float4*>(gam)[tid];
    float4 bv = reinterpret_cast<const float4*>(bet)[tid];
    float4 o;
    o.x = (v.x - mean) * rstd * gv.x + bv.x;
    o.y = (v.y - mean) * rstd * gv.y + bv.y;
    o.z = (v.z - mean) * rstd * gv.z + bv.z;
    o.w = (v.w - mean) * rstd * gv.w + bv.w;
    reinterpret_cast<float4*>(out + (size_t)row * H_)[tid] = o;
}

// ---------------- RoPE -----------------------------------------------------
__global__ void rope_kernel(float* __restrict__ qkv, const float* __restrict__ freqs) {
    int row = blockIdx.x;
    int s   = row & (S_ - 1);
    float* base = qkv + (size_t)row * (3 * H_);
    int tid = threadIdx.x;
    #pragma unroll
    for (int part = 0; part < 2; part++) {
        #pragma unroll
        for (int it = 0; it < 2; it++) {
            int j = tid + it * 256;
            int h = j >> 5, d = j & 31;
            float f = freqs[s * 32 + d];
            float sn, c;
            sincosf(f, &sn, &c);
            float* p = base + part * H_ + h * HD_ + d;
            float x1 = p[0], x2 = p[32];
            p[0]  = x1 * c - x2 * sn;
            p[32] = x2 * c + x1 * sn;
        }
    }
}

// ---------------- TF32 mma helpers ----------------------------------------
__device__ __forceinline__ uint32_t f2tf32(float x) {
    uint32_t y;
    asm("cvt.rna.tf32.f32 %0, %1;" : "=r"(y) : "f"(x));
    return y;
}
__device__ __forceinline__ void ldsm_x4(uint32_t addr, uint32_t& r0, uint32_t& r1,
                                        uint32_t& r2, uint32_t& r3) {
    asm volatile("ldmatrix.sync.aligned.m8n8.x4.shared.b16 {%0,%1,%2,%3}, [%4];"
                 : "=r"(r0), "=r"(r1), "=r"(r2), "=r"(r3) : "r"(addr));
}
__device__ __forceinline__ void mma_tf32(float& c0, float& c1, float& c2, float& c3,
                                         uint32_t a0, uint32_t a1, uint32_t a2, uint32_t a3,
                                         uint32_t b0, uint32_t b1) {
    asm volatile("mma.sync.aligned.m16n8k8.row.col.f32.tf32.tf32.f32 "
                 "{%0,%1,%2,%3},{%4,%5,%6,%7},{%8,%9},{%0,%1,%2,%3};"
                 : "+f"(c0), "+f"(c1), "+f"(c2), "+f"(c3)
                 : "r"(a0), "r"(a1), "r"(a2), "r"(a3), "r"(b0), "r"(b1));
}

// ---------------- TF32 GEMM (validated R2) ---------------------------------
#define EPI_NONE 0
#define EPI_BIAS_RES 1
#define EPI_GELU 2
#define TG_PAD 36

template<int EPI>
__global__ __launch_bounds__(256) void tgemm_kernel(
    const float* __restrict__ A, const float* __restrict__ W,
    const float* __restrict__ bias, const float* __restrict__ res,
    float* __restrict__ C, int M, int N, int K)
{
    __shared__ uint32_t As[128 * TG_PAD];
    __shared__ uint32_t Bt[128 * TG_PAD];

    int tid  = threadIdx.x;
    int lane = tid & 31, w = tid >> 5;
    int wm = (w & 3) * 32;
    int wn = (w >> 2) * 64;
    int bm = blockIdx.y << 7, bn = blockIdx.x << 7;

    float acc[2][8][4];
    #pragma unroll
    for (int mt = 0; mt < 2; mt++)
        #pragma unroll
        for (int nt = 0; nt < 8; nt++)
            #pragma unroll
            for (int u = 0; u < 4; u++) acc[mt][nt][u] = 0.f;

    int arow = tid >> 1, ac0 = (tid & 1) * 16;
    int krow = tid >> 3, nc0 = (tid & 7) * 4;

    const float* Ap = A + (size_t)(bm + arow) * K + ac0;
    const float* Wp = W + (size_t)krow * N + bn + nc0;

    int g = lane >> 3, lr = lane & 7;
    uint32_t as_base = (uint32_t)__cvta_generic_to_shared(As);
    uint32_t bt_base = (uint32_t)__cvta_generic_to_shared(Bt);
    uint32_t a_off = as_base + ((wm + (g & 1) * 8 + lr) * TG_PAD + (g >> 1) * 4) * 4;
    uint32_t b_off = bt_base + ((wn + (g >> 1) * 8 + lr) * TG_PAD + (g & 1) * 4) * 4;

    int nkt = K >> 5;
    for (int kt = 0; kt < nkt; kt++) {
        #pragma unroll
        for (int i = 0; i < 4; i++) {
            float4 v = *reinterpret_cast<const float4*>(Ap + i * 4);
            uint32_t* d = &As[arow * TG_PAD + ac0 + i * 4];
            d[0] = f2tf32(v.x); d[1] = f2tf32(v.y);
            d[2] = f2tf32(v.z); d[3] = f2tf32(v.w);
        }
        #pragma unroll
        for (int i = 0; i < 4; i++) {
            float4 v = *reinterpret_cast<const float4*>(Wp + i * 32);
            int n = nc0 + i * 32;
            Bt[(n + 0) * TG_PAD + krow] = f2tf32(v.x);
            Bt[(n + 1) * TG_PAD + krow] = f2tf32(v.y);
            Bt[(n + 2) * TG_PAD + krow] = f2tf32(v.z);
            Bt[(n + 3) * TG_PAD + krow] = f2tf32(v.w);
        }
        __syncthreads();

        #pragma unroll
        for (int k8 = 0; k8 < 4; k8++) {
            uint32_t a[2][4];
            #pragma unroll
            for (int mt = 0; mt < 2; mt++)
                ldsm_x4(a_off + (mt * 16 * TG_PAD + k8 * 8) * 4,
                        a[mt][0], a[mt][1], a[mt][2], a[mt][3]);
            uint32_t b[8][2];
            #pragma unroll
            for (int np = 0; np < 4; np++) {
                uint32_t r0, r1, r2, r3;
                ldsm_x4(b_off + (np * 16 * TG_PAD + k8 * 8) * 4, r0, r1, r2, r3);
                b[np * 2 + 0][0] = r0; b[np * 2 + 0][1] = r1;
                b[np * 2 + 1][0] = r2; b[np * 2 + 1][1] = r3;
            }
            #pragma unroll
            for (int mt = 0; mt < 2; mt++)
                #pragma unroll
                for (int nt = 0; nt < 8; nt++)
                    mma_tf32(acc[mt][nt][0], acc[mt][nt][1], acc[mt][nt][2], acc[mt][nt][3],
                             a[mt][0], a[mt][1], a[mt][2], a[mt][3],
                             b[nt][0], b[nt][1]);
        }
        __syncthreads();
        Ap += 32;
        Wp += (size_t)32 * N;
    }

    int rbase = bm + wm + (lane >> 2);
    int cbase = bn + wn + (lane & 3) * 2;
    #pragma unroll
    for (int mt = 0; mt < 2; mt++) {
        #pragma unroll
        for (int half = 0; half < 2; half++) {
            int row = rbase + mt * 16 + half * 8;
            #pragma unroll
            for (int nt = 0; nt < 8; nt++) {
                int col = cbase + nt * 8;
                float v0 = acc[mt][nt][half * 2 + 0];
                float v1 = acc[mt][nt][half * 2 + 1];
                if (EPI == EPI_BIAS_RES) {
                    v0 += bias[col]     + res[(size_t)row * N + col];
                    v1 += bias[col + 1] + res[(size_t)row * N + col + 1];
                } else if (EPI == EPI_GELU) {
                    v0 += bias[col];
                    v1 += bias[col + 1];
                    v0 = 0.5f * v0 * (1.0f + erff(v0 * 0.70710678118654752f));
                    v1 = 0.5f * v1 * (1.0f + erff(v1 * 0.70710678118654752f));
                }
                *reinterpret_cast<float2*>(&C[(size_t)row * N + col]) = make_float2(v0, v1);
            }
        }
    }
}

// ---------------- Tensor-core flash attention ------------------------------
// 64 q-rows/block, 4 warps (16 rows each), 64-key tiles, HD=64.
// Qs/Ks/Ps row-major [64][AT_PAD]; Vt transposed [d][key]. All tf32 in smem.
#define AT_PAD 68
#define AT_TILE (64 * AT_PAD)
#define ATTN_SMEM_BYTES (4 * AT_TILE * 4)

template<bool CAUSAL>
__global__ __launch_bounds__(128) void attn_mma_kernel(
    const float* __restrict__ Qp, int q_stride,
    const float* __restrict__ Kp, const float* __restrict__ Vp, int kv_stride,
    int kv_len, const float* __restrict__ maskp,
    float* __restrict__ Op)
{
    extern __shared__ uint32_t sm[];
    uint32_t* Qs = sm;
    uint32_t* Ks = sm + AT_TILE;
    uint32_t* Vt = sm + 2 * AT_TILE;
    uint32_t* Ps = sm + 3 * AT_TILE;

    int tid  = threadIdx.x;
    int lane = tid & 31, w = tid >> 5;
    int g = lane >> 3, lr = lane & 7;
    int q0 = blockIdx.x * 64;
    int h  = blockIdx.y;
    int b  = blockIdx.z;

    uint32_t qs_base = (uint32_t)__cvta_generic_to_shared(Qs);
    uint32_t ks_base = (uint32_t)__cvta_generic_to_shared(Ks);
    uint32_t vt_base = (uint32_t)__cvta_generic_to_shared(Vt);
    uint32_t ps_base = (uint32_t)__cvta_generic_to_shared(Ps);

    uint32_t aq_off = qs_base + ((w * 16 + (g & 1) * 8 + lr) * AT_PAD + (g >> 1) * 4) * 4;
    uint32_t ap_off = ps_base + ((w * 16 + (g & 1) * 8 + lr) * AT_PAD + (g >> 1) * 4) * 4;
    uint32_t bk_row = ((g >> 1) * 8 + lr);
    uint32_t bk_col = (g & 1) * 4;

    // ---- stage Q tile, build Q fragments (kept in regs for whole kernel) --
    #pragma unroll
    for (int it = 0; it < 8; it++) {
        int idx = tid + it * 128;
        int r = idx >> 4, c4 = (idx & 15) * 4;
        float4 v = *reinterpret_cast<const float4*>(
            Qp + (size_t)(b * S_ + q0 + r) * q_stride + h * HD_ + c4);
        uint32_t* d = &Qs[r * AT_PAD + c4];
        d[0] = f2tf32(v.x); d[1] = f2tf32(v.y);
        d[2] = f2tf32(v.z); d[3] = f2tf32(v.w);
    }
    __syncthreads();
    uint32_t qf[8][4];
    #pragma unroll
    for (int k8 = 0; k8 < 8; k8++)
        ldsm_x4(aq_off + k8 * 8 * 4, qf[k8][0], qf[k8][1], qf[k8][2], qf[k8][3]);

    float oacc[8][4];
    #pragma unroll
    for (int nt = 0; nt < 8; nt++)
        #pragma unroll
        for (int u = 0; u < 4; u++) oacc[nt][u] = 0.f;
    float m_i[2] = {-1e30f, -1e30f};
    float l_i[2] = {0.f, 0.f};

    int row_r = lane >> 2;
    int cq    = (lane & 3) * 2;
    int ktiles = CAUSAL ? (q0 / 64 + 1) : (kv_len / 64);
    const float* mrow = maskp ? (maskp + (size_t)b * kv_len) : nullptr;

    for (int kt = 0; kt < ktiles; kt++) {
        int k0 = kt * 64;
        __syncthreads();
        // ---- stage K [key][d] and V transposed [d][key] ----
        #pragma unroll
        for (int it = 0; it < 8; it++) {
            int idx = tid + it * 128;
            int r = idx >> 4, c4 = (idx & 15) * 4;
            size_t off = (size_t)(b * kv_len + k0 + r) * kv_stride + h * HD_ + c4;
            float4 kv = *reinterpret_cast<const float4*>(Kp + off);
            uint32_t* d = &Ks[r * AT_PAD + c4];
            d[0] = f2tf32(kv.x); d[1] = f2tf32(kv.y);
            d[2] = f2tf32(kv.z); d[3] = f2tf32(kv.w);
            float4 vv = *reinterpret_cast<const float4*>(Vp + off);
            Vt[(c4 + 0) * AT_PAD + r] = f2tf32(vv.x);
            Vt[(c4 + 1) * AT_PAD + r] = f2tf32(vv.y);
            Vt[(c4 + 2) * AT_PAD + r] = f2tf32(vv.z);
            Vt[(c4 + 3) * AT_PAD + r] = f2tf32(vv.w);
        }
        __syncthreads();

        // ---- S = Q @ K^T ----
        float sacc[8][4];
        #pragma unroll
        for (int nt = 0; nt < 8; nt++)
            #pragma unroll
            for (int u = 0; u < 4; u++) sacc[nt][u] = 0.f;
        #pragma unroll
        for (int k8 = 0; k8 < 8; k8++) {
            uint32_t bfr[8][2];
            #pragma unroll
            for (int np = 0; np < 4; np++) {
                uint32_t r0, r1, r2, r3;
                ldsm_x4(ks_base + ((np * 16 + bk_row) * AT_PAD + bk_col + k8 * 8) * 4,
                        r0, r1, r2, r3);
                bfr[np * 2 + 0][0] = r0; bfr[np * 2 + 0][1] = r1;
                bfr[np * 2 + 1][0] = r2; bfr[np * 2 + 1][1] = r3;
            }
            #pragma unroll
            for (int nt = 0; nt < 8; nt++)
                mma_tf32(sacc[nt][0], sacc[nt][1], sacc[nt][2], sacc[nt][3],
                         qf[k8][0], qf[k8][1], qf[k8][2], qf[k8][3],
                         bfr[nt][0], bfr[nt][1]);
        }

        // ---- scale + mask ----
        float mv[8][2];
        #pragma unroll
        for (int nt = 0; nt < 8; nt++) {
            mv[nt][0] = mrow ? mrow[k0 + nt * 8 + cq]     : 0.f;
            mv[nt][1] = mrow ? mrow[k0 + nt * 8 + cq + 1] : 0.f;
        }
        #pragma unroll
        for (int nt = 0; nt < 8; nt++)
            #pragma unroll
            for (int u = 0; u < 4; u++) {
                int half = u >> 1;
                float v = sacc[nt][u] * 0.125f + mv[nt][u & 1];
                if (CAUSAL && kt == q0 / 64) {
                    int qrow = q0 + w * 16 + row_r + half * 8;
                    int kcol = k0 + nt * 8 + cq + (u & 1);
                    if (kcol > qrow) v = -1e30f;
                }
                sacc[nt][u] = v;
            }

        // ---- online softmax per row-half ----
        #pragma unroll
        for (int half = 0; half < 2; half++) {
            float mt = -1e30f;
            #pragma unroll
            for (int nt = 0; nt < 8; nt++)
                mt = fmaxf(mt, fmaxf(sacc[nt][half * 2], sacc[nt][half * 2 + 1]));
            mt = fmaxf(mt, __shfl_xor_sync(0xffffffffu, mt, 1));
            mt = fmaxf(mt, __shfl_xor_sync(0xffffffffu, mt, 2));
            float mn = fmaxf(m_i[half], mt);
            float alpha = __expf(m_i[half] - mn);
            m_i[half] = mn;
            float sum = 0.f;
            int prow = (w * 16 + row_r + half * 8) * AT_PAD;
            #pragma unroll
            for (int nt = 0; nt < 8; nt++) {
                float p0 = __expf(sacc[nt][half * 2 + 0] - mn);
                float p1 = __expf(sacc[nt][half * 2 + 1] - mn);
                sum += p0 + p1;
                Ps[prow + nt * 8 + cq + 0] = f2tf32(p0);
                Ps[prow + nt * 8 + cq + 1] = f2tf32(p1);
            }
            sum += __shfl_xor_sync(0xffffffffu, sum, 1);
            sum += __shfl_xor_sync(0xffffffffu, sum, 2);
            l_i[half] = l_i[half] * alpha + sum;
            #pragma unroll
            for (int nt = 0; nt < 8; nt++) {
                oacc[nt][half * 2 + 0] *= alpha;
                oacc[nt][half * 2 + 1] *= alpha;
            }
        }
        // P rows are warp-private, but lanes read each other's words: fence the warp.
        __syncwarp();

        // ---- O += P @ V ----
        #pragma unroll
        for (int k8 = 0; k8 < 8; k8++) {
            uint32_t pa[4];
            ldsm_x4(ap_off + k8 * 8 * 4, pa[0], pa[1], pa[2], pa[3]);
            uint32_t bfr[8][2];
            #pragma unroll
            for (int np = 0; np < 4; np++) {
                uint32_t r0, r1, r2, r3;
                ldsm_x4(vt_base + ((np * 16 + bk_row) * AT_PAD + bk_col + k8 * 8) * 4,
                        r0, r1, r2, r3);
                bfr[np * 2 + 0][0] = r0; bfr[np * 2 + 0][1] = r1;
                bfr[np * 2 + 1][0] = r2; bfr[np * 2 + 1][1] = r3;
            }
            #pragma unroll
            for (int nt = 0; nt < 8; nt++)
                mma_tf32(oacc[nt][0], oacc[nt][1], oacc[nt][2], oacc[nt][3],
                         pa[0], pa[1], pa[2], pa[3],
                         bfr[nt][0], bfr[nt][1]);
        }
    }

    // ---- epilogue ----
    #pragma unroll
    for (int half = 0; half < 2; half++) {
        int q = q0 + w * 16 + row_r + half * 8;
        float inv = 1.0f / l_i[half];
        #pragma unroll
        for (int nt = 0; nt < 8; nt++) {
            float2 o = make_float2(oacc[nt][half * 2 + 0] * inv,
                                   oacc[nt][half * 2 + 1] * inv);
            *reinterpret_cast<float2*>(
                &Op[(size_t)(b * S_ + q) * H_ + h * HD_ + nt * 8 + cq]) = o;
        }
    }
}

// ---------------- launch ---------------------------------------------------
extern "C" void kernel_launch(void* const* d_in, const int* in_sizes, int n_in,
                              void* d_out, int out_size) {
    const float* x      = (const float*)d_in[0];
    const float* rope   = (const float*)d_in[1];
    const float* cond   = (const float*)d_in[3];
    const float* cmask  = (const float*)d_in[4];
    const float* ln1_g  = (const float*)d_in[5];
    const float* ln1_b  = (const float*)d_in[6];
    const float* ln2_g  = (const float*)d_in[7];
    const float* ln2_b  = (const float*)d_in[8];
    const float* lnc_g  = (const float*)d_in[9];
    const float* lnc_b  = (const float*)d_in[10];
    const float* w_qkv  = (const float*)d_in[11];
    const float* w_out  = (const float*)d_in[12];
    const float* b_out  = (const float*)d_in[13];
    const float* w_cq   = (const float*)d_in[14];
    const float* w_ckv  = (const float*)d_in[15];
    const float* w_cout = (const float*)d_in[16];
    const float* b_cout = (const float*)d_in[17];
    const float* w_ff1  = (const float*)d_in[18];
    const float* b_ff1  = (const float*)d_in[19];
    const float* w_ff2  = (const float*)d_in[20];
    const float* b_ff2  = (const float*)d_in[21];
    float* out = (float*)d_out;

    float *h, *qkv, *attn, *xb, *q2, *kvc, *ff;
    cudaGetSymbolAddress((void**)&h,    g_h);
    cudaGetSymbolAddress((void**)&qkv,  g_qkv);
    cudaGetSymbolAddress((void**)&attn, g_attn);
    cudaGetSymbolAddress((void**)&xb,   g_x);
    cudaGetSymbolAddress((void**)&q2,   g_q2);
    cudaGetSymbolAddress((void**)&kvc,  g_kvc);
    cudaGetSymbolAddress((void**)&ff,   g_ff);

    cudaFuncSetAttribute(attn_mma_kernel<true>,  cudaFuncAttributeMaxDynamicSharedMemorySize, ATTN_SMEM_BYTES);
    cudaFuncSetAttribute(attn_mma_kernel<false>, cudaFuncAttributeMaxDynamicSharedMemorySize, ATTN_SMEM_BYTES);

    const int rows = ROWS_;

    // --- self attention ---
    ln_kernel<<<rows, 256>>>(x, ln1_g, ln1_b, h);
    tgemm_kernel<EPI_NONE><<<dim3(3 * H_ / 128, rows / 128), 256>>>(
        h, w_qkv, nullptr, nullptr, qkv, rows, 3 * H_, H_);
    rope_kernel<<<rows, 256>>>(qkv, rope);
    attn_mma_kernel<true><<<dim3(S_ / 64, NH_, B_), 128, ATTN_SMEM_BYTES>>>(
        qkv, 3 * H_, qkv + H_, qkv + 2 * H_, 3 * H_, S_, nullptr, attn);
    tgemm_kernel<EPI_BIAS_RES><<<dim3(H_ / 128, rows / 128), 256>>>(
        attn, w_out, b_out, x, xb, rows, H_, H_);

    // --- cross attention ---
    ln_kernel<<<rows, 256>>>(xb, lnc_g, lnc_b, h);
    tgemm_kernel<EPI_NONE><<<dim3(H_ / 128, rows / 128), 256>>>(
        h, w_cq, nullptr, nullptr, q2, rows, H_, H_);
    tgemm_kernel<EPI_NONE><<<dim3(2 * H_ / 128, (B_ * C_) / 128), 256>>>(
        cond, w_ckv, nullptr, nullptr, kvc, B_ * C_, 2 * H_, H_);
    attn_mma_kernel<false><<<dim3(S_ / 64, NH_, B_), 128, ATTN_SMEM_BYTES>>>(
        q2, H_, kvc, kvc + H_, 2 * H_, C_, cmask, attn);
    tgemm_kernel<EPI_BIAS_RES><<<dim3(H_ / 128, rows / 128), 256>>>(
        attn, w_cout, b_cout, xb, xb, rows, H_, H_);

    // --- FFN ---
    ln_kernel<<<rows, 256>>>(xb, ln2_g, ln2_b, h);
    tgemm_kernel<EPI_GELU><<<dim3(FF_ / 128, rows / 128), 256>>>(
        h, w_ff1, b_ff1, nullptr, ff, rows, FF_, H_);
    tgemm_kernel<EPI_BIAS_RES><<<dim3(H_ / 128, rows / 128), 256>>>(
        ff, w_ff2, b_ff2, xb, out, rows, H_, FF_);
}

// round 5
// speedup vs baseline: 2.7896x; 1.0807x over previous
#include <cuda_runtime.h>
#include <cstdint>

#define B_ 2
#define S_ 2048
#define H_ 1024
#define NH_ 16
#define HD_ 64
#define C_ 256
#define FF_ 4096
#define ROWS_ (B_*S_)

// ---------------- scratch (static device allocations; no cudaMalloc) -------
__device__ float g_h[ROWS_ * H_];
__device__ float g_qkv[ROWS_ * 3 * H_];
__device__ float g_attn[ROWS_ * H_];
__device__ float g_x[ROWS_ * H_];
__device__ float g_q2[ROWS_ * H_];
__device__ float g_kvc[B_ * C_ * 2 * H_];
__device__ float g_ff[ROWS_ * FF_];

// ---------------- LayerNorm ------------------------------------------------
__global__ void ln_kernel(const float* __restrict__ in, const float* __restrict__ gam,
                          const float* __restrict__ bet, float* __restrict__ out) {
    int row = blockIdx.x;
    int tid = threadIdx.x;
    const float4* xr = reinterpret_cast<const float4*>(in + (size_t)row * H_);
    float4 v = xr[tid];
    float s  = v.x + v.y + v.z + v.w;
    float sq = v.x*v.x + v.y*v.y + v.z*v.z + v.w*v.w;
    #pragma unroll
    for (int o = 16; o > 0; o >>= 1) {
        s  += __shfl_xor_sync(0xffffffffu, s,  o);
        sq += __shfl_xor_sync(0xffffffffu, sq, o);
    }
    __shared__ float ss[8], ssq[8];
    __shared__ float sh_mean, sh_rstd;
    if ((tid & 31) == 0) { ss[tid >> 5] = s; ssq[tid >> 5] = sq; }
    __syncthreads();
    if (tid == 0) {
        float ts = 0.f, tq = 0.f;
        #pragma unroll
        for (int i = 0; i < 8; i++) { ts += ss[i]; tq += ssq[i]; }
        float mean = ts * (1.0f / H_);
        float var  = tq * (1.0f / H_) - mean * mean;
        sh_mean = mean;
        sh_rstd = rsqrtf(var + 1e-5f);
    }
    __syncthreads();
    float mean = sh_mean, rstd = sh_rstd;
    float4 gv = reinterpret_cast<const float4*>(gam)[tid];
    float4 bv = reinterpret_cast<const float4*>(bet)[tid];
    float4 o;
    o.x = (v.x - mean) * rstd * gv.x + bv.x;
    o.y = (v.y - mean) * rstd * gv.y + bv.y;
    o.z = (v.z - mean) * rstd * gv.z + bv.z;
    o.w = (v.w - mean) * rstd * gv.w + bv.w;
    reinterpret_cast<float4*>(out + (size_t)row * H_)[tid] = o;
}

// ---------------- RoPE -----------------------------------------------------
__global__ void rope_kernel(float* __restrict__ qkv, const float* __restrict__ freqs) {
    int row = blockIdx.x;
    int s   = row & (S_ - 1);
    float* base = qkv + (size_t)row * (3 * H_);
    int tid = threadIdx.x;
    #pragma unroll
    for (int part = 0; part < 2; part++) {
        #pragma unroll
        for (int it = 0; it < 2; it++) {
            int j = tid + it * 256;
            int h = j >> 5, d = j & 31;
            float f = freqs[s * 32 + d];
            float sn, c;
            sincosf(f, &sn, &c);
            float* p = base + part * H_ + h * HD_ + d;
            float x1 = p[0], x2 = p[32];
            p[0]  = x1 * c - x2 * sn;
            p[32] = x2 * c + x1 * sn;
        }
    }
}

// ---------------- TF32 mma helpers ----------------------------------------
__device__ __forceinline__ uint32_t f2tf32(float x) {
    uint32_t y;
    asm("cvt.rna.tf32.f32 %0, %1;" : "=r"(y) : "f"(x));
    return y;
}
__device__ __forceinline__ void ldsm_x4(uint32_t addr, uint32_t& r0, uint32_t& r1,
                                        uint32_t& r2, uint32_t& r3) {
    asm volatile("ldmatrix.sync.aligned.m8n8.x4.shared.b16 {%0,%1,%2,%3}, [%4];"
                 : "=r"(r0), "=r"(r1), "=r"(r2), "=r"(r3) : "r"(addr));
}
__device__ __forceinline__ void mma_tf32(float& c0, float& c1, float& c2, float& c3,
                                         uint32_t a0, uint32_t a1, uint32_t a2, uint32_t a3,
                                         uint32_t b0, uint32_t b1) {
    asm volatile("mma.sync.aligned.m16n8k8.row.col.f32.tf32.tf32.f32 "
                 "{%0,%1,%2,%3},{%4,%5,%6,%7},{%8,%9},{%0,%1,%2,%3};"
                 : "+f"(c0), "+f"(c1), "+f"(c2), "+f"(c3)
                 : "r"(a0), "r"(a1), "r"(a2), "r"(a3), "r"(b0), "r"(b1));
}

// ---------------- TF32 GEMM with register-prefetch pipeline ----------------
#define EPI_NONE 0
#define EPI_BIAS_RES 1
#define EPI_GELU 2
#define TG_PAD 36

template<int EPI>
__global__ __launch_bounds__(256) void tgemm_kernel(
    const float* __restrict__ A, const float* __restrict__ W,
    const float* __restrict__ bias, const float* __restrict__ res,
    float* __restrict__ C, int M, int N, int K)
{
    __shared__ uint32_t As[128 * TG_PAD];
    __shared__ uint32_t Bt[128 * TG_PAD];

    int tid  = threadIdx.x;
    int lane = tid & 31, w = tid >> 5;
    int wm = (w & 3) * 32;
    int wn = (w >> 2) * 64;
    int bm = blockIdx.y << 7, bn = blockIdx.x << 7;

    float acc[2][8][4];
    #pragma unroll
    for (int mt = 0; mt < 2; mt++)
        #pragma unroll
        for (int nt = 0; nt < 8; nt++)
            #pragma unroll
            for (int u = 0; u < 4; u++) acc[mt][nt][u] = 0.f;

    int arow = tid >> 1, ac0 = (tid & 1) * 16;
    int krow = tid >> 3, nc0 = (tid & 7) * 4;

    const float* Ap = A + (size_t)(bm + arow) * K + ac0;
    const float* Wp = W + (size_t)krow * N + bn + nc0;

    int g = lane >> 3, lr = lane & 7;
    uint32_t as_base = (uint32_t)__cvta_generic_to_shared(As);
    uint32_t bt_base = (uint32_t)__cvta_generic_to_shared(Bt);
    uint32_t a_off = as_base + ((wm + (g & 1) * 8 + lr) * TG_PAD + (g >> 1) * 4) * 4;
    uint32_t b_off = bt_base + ((wn + (g >> 1) * 8 + lr) * TG_PAD + (g & 1) * 4) * 4;

    // prologue: load first tile into registers
    float4 ra[4], rw[4];
    #pragma unroll
    for (int i = 0; i < 4; i++) {
        ra[i] = *reinterpret_cast<const float4*>(Ap + i * 4);
        rw[i] = *reinterpret_cast<const float4*>(Wp + i * 32);
    }

    int nkt = K >> 5;
    for (int kt = 0; kt < nkt; kt++) {
        // ---- store staged regs to smem (with tf32 convert) ----
        #pragma unroll
        for (int i = 0; i < 4; i++) {
            uint32_t* d = &As[arow * TG_PAD + ac0 + i * 4];
            d[0] = f2tf32(ra[i].x); d[1] = f2tf32(ra[i].y);
            d[2] = f2tf32(ra[i].z); d[3] = f2tf32(ra[i].w);
            int n = nc0 + i * 32;
            Bt[(n + 0) * TG_PAD + krow] = f2tf32(rw[i].x);
            Bt[(n + 1) * TG_PAD + krow] = f2tf32(rw[i].y);
            Bt[(n + 2) * TG_PAD + krow] = f2tf32(rw[i].z);
            Bt[(n + 3) * TG_PAD + krow] = f2tf32(rw[i].w);
        }
        __syncthreads();

        // ---- prefetch next tile (gmem latency overlaps mma compute) ----
        if (kt + 1 < nkt) {
            Ap += 32;
            Wp += (size_t)32 * N;
            #pragma unroll
            for (int i = 0; i < 4; i++) {
                ra[i] = *reinterpret_cast<const float4*>(Ap + i * 4);
                rw[i] = *reinterpret_cast<const float4*>(Wp + i * 32);
            }
        }

        // ---- compute ----
        #pragma unroll
        for (int k8 = 0; k8 < 4; k8++) {
            uint32_t a[2][4];
            #pragma unroll
            for (int mt = 0; mt < 2; mt++)
                ldsm_x4(a_off + (mt * 16 * TG_PAD + k8 * 8) * 4,
                        a[mt][0], a[mt][1], a[mt][2], a[mt][3]);
            uint32_t b[8][2];
            #pragma unroll
            for (int np = 0; np < 4; np++) {
                uint32_t r0, r1, r2, r3;
                ldsm_x4(b_off + (np * 16 * TG_PAD + k8 * 8) * 4, r0, r1, r2, r3);
                b[np * 2 + 0][0] = r0; b[np * 2 + 0][1] = r1;
                b[np * 2 + 1][0] = r2; b[np * 2 + 1][1] = r3;
            }
            #pragma unroll
            for (int mt = 0; mt < 2; mt++)
                #pragma unroll
                for (int nt = 0; nt < 8; nt++)
                    mma_tf32(acc[mt][nt][0], acc[mt][nt][1], acc[mt][nt][2], acc[mt][nt][3],
                             a[mt][0], a[mt][1], a[mt][2], a[mt][3],
                             b[nt][0], b[nt][1]);
        }
        __syncthreads();
    }

    int rbase = bm + wm + (lane >> 2);
    int cbase = bn + wn + (lane & 3) * 2;
    #pragma unroll
    for (int mt = 0; mt < 2; mt++) {
        #pragma unroll
        for (int half = 0; half < 2; half++) {
            int row = rbase + mt * 16 + half * 8;
            #pragma unroll
            for (int nt = 0; nt < 8; nt++) {
                int col = cbase + nt * 8;
                float v0 = acc[mt][nt][half * 2 + 0];
                float v1 = acc[mt][nt][half * 2 + 1];
                if (EPI == EPI_BIAS_RES) {
                    v0 += bias[col]     + res[(size_t)row * N + col];
                    v1 += bias[col + 1] + res[(size_t)row * N + col + 1];
                } else if (EPI == EPI_GELU) {
                    v0 += bias[col];
                    v1 += bias[col + 1];
                    v0 = 0.5f * v0 * (1.0f + erff(v0 * 0.70710678118654752f));
                    v1 = 0.5f * v1 * (1.0f + erff(v1 * 0.70710678118654752f));
                }
                *reinterpret_cast<float2*>(&C[(size_t)row * N + col]) = make_float2(v0, v1);
            }
        }
    }
}

// ---------------- Tensor-core flash attention ------------------------------
// 64 q-rows/block, 4 warps, 64-key tiles, HD=64.
// smem: 3 tiles — Qs (aliased by Ps after prologue), Ks, Vt.
#define AT_PAD 68
#define AT_TILE (64 * AT_PAD)
#define ATTN_SMEM_BYTES (3 * AT_TILE * 4)

template<bool CAUSAL>
__global__ __launch_bounds__(128, 3) void attn_mma_kernel(
    const float* __restrict__ Qp, int q_stride,
    const float* __restrict__ Kp, const float* __restrict__ Vp, int kv_stride,
    int kv_len, const float* __restrict__ maskp,
    float* __restrict__ Op)
{
    extern __shared__ uint32_t sm[];
    uint32_t* Qs = sm;                 // dead after qf fragments built
    uint32_t* Ks = sm + AT_TILE;
    uint32_t* Vt = sm + 2 * AT_TILE;
    uint32_t* Ps = sm;                 // aliases Qs

    int tid  = threadIdx.x;
    int lane = tid & 31, w = tid >> 5;
    int g = lane >> 3, lr = lane & 7;
    int q0 = blockIdx.x * 64;
    int h  = blockIdx.y;
    int b  = blockIdx.z;

    uint32_t qs_base = (uint32_t)__cvta_generic_to_shared(Qs);
    uint32_t ks_base = (uint32_t)__cvta_generic_to_shared(Ks);
    uint32_t vt_base = (uint32_t)__cvta_generic_to_shared(Vt);
    uint32_t ps_base = qs_base;

    uint32_t aq_off = qs_base + ((w * 16 + (g & 1) * 8 + lr) * AT_PAD + (g >> 1) * 4) * 4;
    uint32_t ap_off = ps_base + ((w * 16 + (g & 1) * 8 + lr) * AT_PAD + (g >> 1) * 4) * 4;
    uint32_t bk_row = ((g >> 1) * 8 + lr);
    uint32_t bk_col = (g & 1) * 4;

    // ---- stage Q tile, build Q fragments (kept in regs for whole kernel) --
    #pragma unroll
    for (int it = 0; it < 8; it++) {
        int idx = tid + it * 128;
        int r = idx >> 4, c4 = (idx & 15) * 4;
        float4 v = *reinterpret_cast<const float4*>(
            Qp + (size_t)(b * S_ + q0 + r) * q_stride + h * HD_ + c4);
        uint32_t* d = &Qs[r * AT_PAD + c4];
        d[0] = f2tf32(v.x); d[1] = f2tf32(v.y);
        d[2] = f2tf32(v.z); d[3] = f2tf32(v.w);
    }
    __syncthreads();
    uint32_t qf[8][4];
    #pragma unroll
    for (int k8 = 0; k8 < 8; k8++)
        ldsm_x4(aq_off + k8 * 8 * 4, qf[k8][0], qf[k8][1], qf[k8][2], qf[k8][3]);

    float oacc[8][4];
    #pragma unroll
    for (int nt = 0; nt < 8; nt++)
        #pragma unroll
        for (int u = 0; u < 4; u++) oacc[nt][u] = 0.f;
    float m_i[2] = {-1e30f, -1e30f};
    float l_i[2] = {0.f, 0.f};

    int row_r = lane >> 2;
    int cq    = (lane & 3) * 2;
    int ktiles = CAUSAL ? (q0 / 64 + 1) : (kv_len / 64);
    const float* mrow = maskp ? (maskp + (size_t)b * kv_len) : nullptr;

    for (int kt = 0; kt < ktiles; kt++) {
        int k0 = kt * 64;
        __syncthreads();   // prior-iter Ks/Vt/Ps reads complete; Qs free after prologue
        // ---- stage K [key][d] and V transposed [d][key] ----
        #pragma unroll
        for (int it = 0; it < 8; it++) {
            int idx = tid + it * 128;
            int r = idx >> 4, c4 = (idx & 15) * 4;
            size_t off = (size_t)(b * kv_len + k0 + r) * kv_stride + h * HD_ + c4;
            float4 kv = *reinterpret_cast<const float4*>(Kp + off);
            uint32_t* d = &Ks[r * AT_PAD + c4];
            d[0] = f2tf32(kv.x); d[1] = f2tf32(kv.y);
            d[2] = f2tf32(kv.z); d[3] = f2tf32(kv.w);
            float4 vv = *reinterpret_cast<const float4*>(Vp + off);
            Vt[(c4 + 0) * AT_PAD + r] = f2tf32(vv.x);
            Vt[(c4 + 1) * AT_PAD + r] = f2tf32(vv.y);
            Vt[(c4 + 2) * AT_PAD + r] = f2tf32(vv.z);
            Vt[(c4 + 3) * AT_PAD + r] = f2tf32(vv.w);
        }
        __syncthreads();

        // ---- S = Q @ K^T ----
        float sacc[8][4];
        #pragma unroll
        for (int nt = 0; nt < 8; nt++)
            #pragma unroll
            for (int u = 0; u < 4; u++) sacc[nt][u] = 0.f;
        #pragma unroll
        for (int k8 = 0; k8 < 8; k8++) {
            uint32_t bfr[8][2];
            #pragma unroll
            for (int np = 0; np < 4; np++) {
                uint32_t r0, r1, r2, r3;
                ldsm_x4(ks_base + ((np * 16 + bk_row) * AT_PAD + bk_col + k8 * 8) * 4,
                        r0, r1, r2, r3);
                bfr[np * 2 + 0][0] = r0; bfr[np * 2 + 0][1] = r1;
                bfr[np * 2 + 1][0] = r2; bfr[np * 2 + 1][1] = r3;
            }
            #pragma unroll
            for (int nt = 0; nt < 8; nt++)
                mma_tf32(sacc[nt][0], sacc[nt][1], sacc[nt][2], sacc[nt][3],
                         qf[k8][0], qf[k8][1], qf[k8][2], qf[k8][3],
                         bfr[nt][0], bfr[nt][1]);
        }

        // ---- scale + mask ----
        float mv[8][2];
        #pragma unroll
        for (int nt = 0; nt < 8; nt++) {
            mv[nt][0] = mrow ? mrow[k0 + nt * 8 + cq]     : 0.f;
            mv[nt][1] = mrow ? mrow[k0 + nt * 8 + cq + 1] : 0.f;
        }
        #pragma unroll
        for (int nt = 0; nt < 8; nt++)
            #pragma unroll
            for (int u = 0; u < 4; u++) {
                int half = u >> 1;
                float v = sacc[nt][u] * 0.125f + mv[nt][u & 1];
                if (CAUSAL && kt == q0 / 64) {
                    int qrow = q0 + w * 16 + row_r + half * 8;
                    int kcol = k0 + nt * 8 + cq + (u & 1);
                    if (kcol > qrow) v = -1e30f;
                }
                sacc[nt][u] = v;
            }

        // ---- online softmax per row-half ----
        #pragma unroll
        for (int half = 0; half < 2; half++) {
            float mt = -1e30f;
            #pragma unroll
            for (int nt = 0; nt < 8; nt++)
                mt = fmaxf(mt, fmaxf(sacc[nt][half * 2], sacc[nt][half * 2 + 1]));
            mt = fmaxf(mt, __shfl_xor_sync(0xffffffffu, mt, 1));
            mt = fmaxf(mt, __shfl_xor_sync(0xffffffffu, mt, 2));
            float mn = fmaxf(m_i[half], mt);
            float alpha = __expf(m_i[half] - mn);
            m_i[half] = mn;
            float sum = 0.f;
            int prow = (w * 16 + row_r + half * 8) * AT_PAD;
            #pragma unroll
            for (int nt = 0; nt < 8; nt++) {
                float p0 = __expf(sacc[nt][half * 2 + 0] - mn);
                float p1 = __expf(sacc[nt][half * 2 + 1] - mn);
                sum += p0 + p1;
                Ps[prow + nt * 8 + cq + 0] = f2tf32(p0);
                Ps[prow + nt * 8 + cq + 1] = f2tf32(p1);
            }
            sum += __shfl_xor_sync(0xffffffffu, sum, 1);
            sum += __shfl_xor_sync(0xffffffffu, sum, 2);
            l_i[half] = l_i[half] * alpha + sum;
            #pragma unroll
            for (int nt = 0; nt < 8; nt++) {
                oacc[nt][half * 2 + 0] *= alpha;
                oacc[nt][half * 2 + 1] *= alpha;
            }
        }
        // P rows are warp-private, but lanes read each other's words: fence the warp.
        __syncwarp();

        // ---- O += P @ V ----
        #pragma unroll
        for (int k8 = 0; k8 < 8; k8++) {
            uint32_t pa[4];
            ldsm_x4(ap_off + k8 * 8 * 4, pa[0], pa[1], pa[2], pa[3]);
            uint32_t bfr[8][2];
            #pragma unroll
            for (int np = 0; np < 4; np++) {
                uint32_t r0, r1, r2, r3;
                ldsm_x4(vt_base + ((np * 16 + bk_row) * AT_PAD + bk_col + k8 * 8) * 4,
                        r0, r1, r2, r3);
                bfr[np * 2 + 0][0] = r0; bfr[np * 2 + 0][1] = r1;
                bfr[np * 2 + 1][0] = r2; bfr[np * 2 + 1][1] = r3;
            }
            #pragma unroll
            for (int nt = 0; nt < 8; nt++)
                mma_tf32(oacc[nt][0], oacc[nt][1], oacc[nt][2], oacc[nt][3],
                         pa[0], pa[1], pa[2], pa[3],
                         bfr[nt][0], bfr[nt][1]);
        }
    }

    // ---- epilogue ----
    #pragma unroll
    for (int half = 0; half < 2; half++) {
        int q = q0 + w * 16 + row_r + half * 8;
        float inv = 1.0f / l_i[half];
        #pragma unroll
        for (int nt = 0; nt < 8; nt++) {
            float2 o = make_float2(oacc[nt][half * 2 + 0] * inv,
                                   oacc[nt][half * 2 + 1] * inv);
            *reinterpret_cast<float2*>(
                &Op[(size_t)(b * S_ + q) * H_ + h * HD_ + nt * 8 + cq]) = o;
        }
    }
}

// ---------------- launch ---------------------------------------------------
extern "C" void kernel_launch(void* const* d_in, const int* in_sizes, int n_in,
                              void* d_out, int out_size) {
    const float* x      = (const float*)d_in[0];
    const float* rope   = (const float*)d_in[1];
    const float* cond   = (const float*)d_in[3];
    const float* cmask  = (const float*)d_in[4];
    const float* ln1_g  = (const float*)d_in[5];
    const float* ln1_b  = (const float*)d_in[6];
    const float* ln2_g  = (const float*)d_in[7];
    const float* ln2_b  = (const float*)d_in[8];
    const float* lnc_g  = (const float*)d_in[9];
    const float* lnc_b  = (const float*)d_in[10];
    const float* w_qkv  = (const float*)d_in[11];
    const float* w_out  = (const float*)d_in[12];
    const float* b_out  = (const float*)d_in[13];
    const float* w_cq   = (const float*)d_in[14];
    const float* w_ckv  = (const float*)d_in[15];
    const float* w_cout = (const float*)d_in[16];
    const float* b_cout = (const float*)d_in[17];
    const float* w_ff1  = (const float*)d_in[18];
    const float* b_ff1  = (const float*)d_in[19];
    const float* w_ff2  = (const float*)d_in[20];
    const float* b_ff2  = (const float*)d_in[21];
    float* out = (float*)d_out;

    float *h, *qkv, *attn, *xb, *q2, *kvc, *ff;
    cudaGetSymbolAddress((void**)&h,    g_h);
    cudaGetSymbolAddress((void**)&qkv,  g_qkv);
    cudaGetSymbolAddress((void**)&attn, g_attn);
    cudaGetSymbolAddress((void**)&xb,   g_x);
    cudaGetSymbolAddress((void**)&q2,   g_q2);
    cudaGetSymbolAddress((void**)&kvc,  g_kvc);
    cudaGetSymbolAddress((void**)&ff,   g_ff);

    cudaFuncSetAttribute(attn_mma_kernel<true>,  cudaFuncAttributeMaxDynamicSharedMemorySize, ATTN_SMEM_BYTES);
    cudaFuncSetAttribute(attn_mma_kernel<false>, cudaFuncAttributeMaxDynamicSharedMemorySize, ATTN_SMEM_BYTES);

    const int rows = ROWS_;

    // --- self attention ---
    ln_kernel<<<rows, 256>>>(x, ln1_g, ln1_b, h);
    tgemm_kernel<EPI_NONE><<<dim3(3 * H_ / 128, rows / 128), 256>>>(
        h, w_qkv, nullptr, nullptr, qkv, rows, 3 * H_, H_);
    rope_kernel<<<rows, 256>>>(qkv, rope);
    attn_mma_kernel<true><<<dim3(S_ / 64, NH_, B_), 128, ATTN_SMEM_BYTES>>>(
        qkv, 3 * H_, qkv + H_, qkv + 2 * H_, 3 * H_, S_, nullptr, attn);
    tgemm_kernel<EPI_BIAS_RES><<<dim3(H_ / 128, rows / 128), 256>>>(
        attn, w_out, b_out, x, xb, rows, H_, H_);

    // --- cross attention ---
    ln_kernel<<<rows, 256>>>(xb, lnc_g, lnc_b, h);
    tgemm_kernel<EPI_NONE><<<dim3(H_ / 128, rows / 128), 256>>>(
        h, w_cq, nullptr, nullptr, q2, rows, H_, H_);
    tgemm_kernel<EPI_NONE><<<dim3(2 * H_ / 128, (B_ * C_) / 128), 256>>>(
        cond, w_ckv, nullptr, nullptr, kvc, B_ * C_, 2 * H_, H_);
    attn_mma_kernel<false><<<dim3(S_ / 64, NH_, B_), 128, ATTN_SMEM_BYTES>>>(
        q2, H_, kvc, kvc + H_, 2 * H_, C_, cmask, attn);
    tgemm_kernel<EPI_BIAS_RES><<<dim3(H_ / 128, rows / 128), 256>>>(
        attn, w_cout, b_cout, xb, xb, rows, H_, H_);

    // --- FFN ---
    ln_kernel<<<rows, 256>>>(xb, ln2_g, ln2_b, h);
    tgemm_kernel<EPI_GELU><<<dim3(FF_ / 128, rows / 128), 256>>>(
        h, w_ff1, b_ff1, nullptr, ff, rows, FF_, H_);
    tgemm_kernel<EPI_BIAS_RES><<<dim3(H_ / 128, rows / 128), 256>>>(
        ff, w_ff2, b_ff2, xb, out, rows, H_, FF_);
}

// round 8
// speedup vs baseline: 2.8537x; 1.0230x over previous
#include <cuda_runtime.h>
#include <cstdint>

#define B_ 2
#define S_ 2048
#define H_ 1024
#define NH_ 16
#define HD_ 64
#define C_ 256
#define FF_ 4096
#define ROWS_ (B_*S_)

// ---------------- scratch (static device allocations; no cudaMalloc) -------
__device__ float g_h[ROWS_ * H_];
__device__ float g_qkv[ROWS_ * 3 * H_];
__device__ float g_attn[ROWS_ * H_];
__device__ float g_x[ROWS_ * H_];
__device__ float g_q2[ROWS_ * H_];
__device__ float g_kvc[B_ * C_ * 2 * H_];
__device__ float g_ff[ROWS_ * FF_];
__device__ float g_rtab[S_ * 32 * 2];   // per (s, d<32): cos, sin

// ---------------- LayerNorm ------------------------------------------------
__global__ void ln_kernel(const float* __restrict__ in, const float* __restrict__ gam,
                          const float* __restrict__ bet, float* __restrict__ out) {
    int row = blockIdx.x;
    int tid = threadIdx.x;
    const float4* xr = reinterpret_cast<const float4*>(in + (size_t)row * H_);
    float4 v = xr[tid];
    float s  = v.x + v.y + v.z + v.w;
    float sq = v.x*v.x + v.y*v.y + v.z*v.z + v.w*v.w;
    #pragma unroll
    for (int o = 16; o > 0; o >>= 1) {
        s  += __shfl_xor_sync(0xffffffffu, s,  o);
        sq += __shfl_xor_sync(0xffffffffu, sq, o);
    }
    __shared__ float ss[8], ssq[8];
    __shared__ float sh_mean, sh_rstd;
    if ((tid & 31) == 0) { ss[tid >> 5] = s; ssq[tid >> 5] = sq; }
    __syncthreads();
    if (tid == 0) {
        float ts = 0.f, tq = 0.f;
        #pragma unroll
        for (int i = 0; i < 8; i++) { ts += ss[i]; tq += ssq[i]; }
        float mean = ts * (1.0f / H_);
        float var  = tq * (1.0f / H_) - mean * mean;
        sh_mean = mean;
        sh_rstd = rsqrtf(var + 1e-5f);
    }
    __syncthreads();
    float mean = sh_mean, rstd = sh_rstd;
    float4 gv = reinterpret_cast<const float4*>(gam)[tid];
    float4 bv = reinterpret_cast<const float4*>(bet)[tid];
    float4 o;
    o.x = (v.x - mean) * rstd * gv.x + bv.x;
    o.y = (v.y - mean) * rstd * gv.y + bv.y;
    o.z = (v.z - mean) * rstd * gv.z + bv.z;
    o.w = (v.w - mean) * rstd * gv.w + bv.w;
    reinterpret_cast<float4*>(out + (size_t)row * H_)[tid] = o;
}

// ---------------- RoPE table + apply ---------------------------------------
__global__ void rope_table_kernel(const float* __restrict__ freqs, float* __restrict__ tab) {
    int idx = blockIdx.x * 256 + threadIdx.x;   // 0 .. S_*32-1
    float f = freqs[idx];
    float sn, c;
    sincosf(f, &sn, &c);
    tab[idx * 2 + 0] = c;
    tab[idx * 2 + 1] = sn;
}

__global__ void rope_kernel(float* __restrict__ qkv, const float* __restrict__ tab) {
    int row = blockIdx.x;
    int s   = row & (S_ - 1);
    float* base = qkv + (size_t)row * (3 * H_);
    int tid = threadIdx.x;
    #pragma unroll
    for (int part = 0; part < 2; part++) {
        #pragma unroll
        for (int it = 0; it < 2; it++) {
            int j = tid + it * 256;
            int h = j >> 5, d = j & 31;
            float2 cs = *reinterpret_cast<const float2*>(&tab[(s * 32 + d) * 2]);
            float* p = base + part * H_ + h * HD_ + d;
            float x1 = p[0], x2 = p[32];
            p[0]  = x1 * cs.x - x2 * cs.y;
            p[32] = x2 * cs.x + x1 * cs.y;
        }
    }
}

// ---------------- TF32 mma helpers ----------------------------------------
__device__ __forceinline__ uint32_t f2tf32(float x) {
    uint32_t y;
    asm("cvt.rna.tf32.f32 %0, %1;" : "=r"(y) : "f"(x));
    return y;
}
__device__ __forceinline__ void ldsm_x4(uint32_t addr, uint32_t& r0, uint32_t& r1,
                                        uint32_t& r2, uint32_t& r3) {
    asm volatile("ldmatrix.sync.aligned.m8n8.x4.shared.b16 {%0,%1,%2,%3}, [%4];"
                 : "=r"(r0), "=r"(r1), "=r"(r2), "=r"(r3) : "r"(addr));
}
__device__ __forceinline__ void mma_tf32(float& c0, float& c1, float& c2, float& c3,
                                         uint32_t a0, uint32_t a1, uint32_t a2, uint32_t a3,
                                         uint32_t b0, uint32_t b1) {
    asm volatile("mma.sync.aligned.m16n8k8.row.col.f32.tf32.tf32.f32 "
                 "{%0,%1,%2,%3},{%4,%5,%6,%7},{%8,%9},{%0,%1,%2,%3};"
                 : "+f"(c0), "+f"(c1), "+f"(c2), "+f"(c3)
                 : "r"(a0), "r"(a1), "r"(a2), "r"(a3), "r"(b0), "r"(b1));
}

// ---------------- TF32 GEMM: double-buffered smem pipeline -----------------
#define EPI_NONE 0
#define EPI_BIAS_RES 1
#define EPI_GELU 2
#define TG_PAD 36
#define TG_STG (128 * TG_PAD)                 // uint32 per tile buffer
#define TG_SMEM_BYTES (4 * TG_STG * 4)        // As0,Bt0,As1,Bt1 = 73728 B

template<int EPI>
__global__ __launch_bounds__(256) void tgemm_kernel(
    const float* __restrict__ A, const float* __restrict__ W,
    const float* __restrict__ bias, const float* __restrict__ res,
    float* __restrict__ C, int M, int N, int K)
{
    extern __shared__ uint32_t smg[];
    // layout: stage0 {As,Bt}, stage1 {As,Bt}
    uint32_t* Asb = smg;                      // + s*(2*TG_STG)
    uint32_t* Btb = smg + TG_STG;

    int tid  = threadIdx.x;
    int lane = tid & 31, w = tid >> 5;
    int wm = (w & 3) * 32;
    int wn = (w >> 2) * 64;
    int bm = blockIdx.y << 7, bn = blockIdx.x << 7;

    float acc[2][8][4];
    #pragma unroll
    for (int mt = 0; mt < 2; mt++)
        #pragma unroll
        for (int nt = 0; nt < 8; nt++)
            #pragma unroll
            for (int u = 0; u < 4; u++) acc[mt][nt][u] = 0.f;

    int arow = tid >> 1, ac0 = (tid & 1) * 16;
    int krow = tid >> 3, nc0 = (tid & 7) * 4;

    const float* Ap = A + (size_t)(bm + arow) * K + ac0;
    const float* Wp = W + (size_t)krow * N + bn + nc0;

    int g = lane >> 3, lr = lane & 7;
    uint32_t sm_base = (uint32_t)__cvta_generic_to_shared(smg);
    const uint32_t STGB = 2 * TG_STG * 4;     // bytes per stage
    uint32_t a_off0 = sm_base + ((wm + (g & 1) * 8 + lr) * TG_PAD + (g >> 1) * 4) * 4;
    uint32_t b_off0 = sm_base + TG_STG * 4 +
                      ((wn + (g >> 1) * 8 + lr) * TG_PAD + (g & 1) * 4) * 4;

    // prologue: tile 0 → regs → stage 0
    float4 ra[4], rw[4];
    #pragma unroll
    for (int i = 0; i < 4; i++) {
        ra[i] = *reinterpret_cast<const float4*>(Ap + i * 4);
        rw[i] = *reinterpret_cast<const float4*>(Wp + i * 32);
    }
    #pragma unroll
    for (int i = 0; i < 4; i++) {
        uint32_t* d = &Asb[arow * TG_PAD + ac0 + i * 4];
        d[0] = f2tf32(ra[i].x); d[1] = f2tf32(ra[i].y);
        d[2] = f2tf32(ra[i].z); d[3] = f2tf32(ra[i].w);
        int n = nc0 + i * 32;
        Btb[(n + 0) * TG_PAD + krow] = f2tf32(rw[i].x);
        Btb[(n + 1) * TG_PAD + krow] = f2tf32(rw[i].y);
        Btb[(n + 2) * TG_PAD + krow] = f2tf32(rw[i].z);
        Btb[(n + 3) * TG_PAD + krow] = f2tf32(rw[i].w);
    }
    __syncthreads();

    int nkt = K >> 5;
    for (int kt = 0; kt < nkt; kt++) {
        int cur = kt & 1, nxt = cur ^ 1;
        // prefetch gmem tile kt+1 into registers
        if (kt + 1 < nkt) {
            Ap += 32;
            Wp += (size_t)32 * N;
            #pragma unroll
            for (int i = 0; i < 4; i++) {
                ra[i] = *reinterpret_cast<const float4*>(Ap + i * 4);
                rw[i] = *reinterpret_cast<const float4*>(Wp + i * 32);
            }
        }

        // compute from stage cur
        uint32_t a_off = a_off0 + cur * STGB;
        uint32_t b_off = b_off0 + cur * STGB;
        #pragma unroll
        for (int k8 = 0; k8 < 4; k8++) {
            uint32_t a[2][4];
            #pragma unroll
            for (int mt = 0; mt < 2; mt++)
                ldsm_x4(a_off + (mt * 16 * TG_PAD + k8 * 8) * 4,
                        a[mt][0], a[mt][1], a[mt][2], a[mt][3]);
            uint32_t b[8][2];
            #pragma unroll
            for (int np = 0; np < 4; np++) {
                uint32_t r0, r1, r2, r3;
                ldsm_x4(b_off + (np * 16 * TG_PAD + k8 * 8) * 4, r0, r1, r2, r3);
                b[np * 2 + 0][0] = r0; b[np * 2 + 0][1] = r1;
                b[np * 2 + 1][0] = r2; b[np * 2 + 1][1] = r3;
            }
            #pragma unroll
            for (int mt = 0; mt < 2; mt++)
                #pragma unroll
                for (int nt = 0; nt < 8; nt++)
                    mma_tf32(acc[mt][nt][0], acc[mt][nt][1], acc[mt][nt][2], acc[mt][nt][3],
                             a[mt][0], a[mt][1], a[mt][2], a[mt][3],
                             b[nt][0], b[nt][1]);
        }

        // store regs tile kt+1 into stage nxt (its last readers synced at iter kt-1)
        if (kt + 1 < nkt) {
            uint32_t* As = Asb + nxt * 2 * TG_STG;
            uint32_t* Bt = Btb + nxt * 2 * TG_STG;
            #pragma unroll
            for (int i = 0; i < 4; i++) {
                uint32_t* d = &As[arow * TG_PAD + ac0 + i * 4];
                d[0] = f2tf32(ra[i].x); d[1] = f2tf32(ra[i].y);
                d[2] = f2tf32(ra[i].z); d[3] = f2tf32(ra[i].w);
                int n = nc0 + i * 32;
                Bt[(n + 0) * TG_PAD + krow] = f2tf32(rw[i].x);
                Bt[(n + 1) * TG_PAD + krow] = f2tf32(rw[i].y);
                Bt[(n + 2) * TG_PAD + krow] = f2tf32(rw[i].z);
                Bt[(n + 3) * TG_PAD + krow] = f2tf32(rw[i].w);
            }
            __syncthreads();
        }
    }

    int rbase = bm + wm + (lane >> 2);
    int cbase = bn + wn + (lane & 3) * 2;
    #pragma unroll
    for (int mt = 0; mt < 2; mt++) {
        #pragma unroll
        for (int half = 0; half < 2; half++) {
            int row = rbase + mt * 16 + half * 8;
            #pragma unroll
            for (int nt = 0; nt < 8; nt++) {
                int col = cbase + nt * 8;
                float v0 = acc[mt][nt][half * 2 + 0];
                float v1 = acc[mt][nt][half * 2 + 1];
                if (EPI == EPI_BIAS_RES) {
                    v0 += bias[col]     + res[(size_t)row * N + col];
                    v1 += bias[col + 1] + res[(size_t)row * N + col + 1];
                } else if (EPI == EPI_GELU) {
                    v0 += bias[col];
                    v1 += bias[col + 1];
                    v0 = 0.5f * v0 * (1.0f + erff(v0 * 0.70710678118654752f));
                    v1 = 0.5f * v1 * (1.0f + erff(v1 * 0.70710678118654752f));
                }
                *reinterpret_cast<float2*>(&C[(size_t)row * N + col]) = make_float2(v0, v1);
            }
        }
    }
}

// ---------------- Tensor-core flash attention (validated R5) ---------------
#define AT_PAD 68
#define AT_TILE (64 * AT_PAD)
#define ATTN_SMEM_BYTES (3 * AT_TILE * 4)

template<bool CAUSAL>
__global__ __launch_bounds__(128, 3) void attn_mma_kernel(
    const float* __restrict__ Qp, int q_stride,
    const float* __restrict__ Kp, const float* __restrict__ Vp, int kv_stride,
    int kv_len, const float* __restrict__ maskp,
    float* __restrict__ Op)
{
    extern __shared__ uint32_t sm[];
    uint32_t* Qs = sm;
    uint32_t* Ks = sm + AT_TILE;
    uint32_t* Vt = sm + 2 * AT_TILE;
    uint32_t* Ps = sm;

    int tid  = threadIdx.x;
    int lane = tid & 31, w = tid >> 5;
    int g = lane >> 3, lr = lane & 7;
    int q0 = blockIdx.x * 64;
    int h  = blockIdx.y;
    int b  = blockIdx.z;

    uint32_t qs_base = (uint32_t)__cvta_generic_to_shared(Qs);
    uint32_t ks_base = (uint32_t)__cvta_generic_to_shared(Ks);
    uint32_t vt_base = (uint32_t)__cvta_generic_to_shared(Vt);
    uint32_t ps_base = qs_base;

    uint32_t aq_off = qs_base + ((w * 16 + (g & 1) * 8 + lr) * AT_PAD + (g >> 1) * 4) * 4;
    uint32_t ap_off = ps_base + ((w * 16 + (g & 1) * 8 + lr) * AT_PAD + (g >> 1) * 4) * 4;
    uint32_t bk_row = ((g >> 1) * 8 + lr);
    uint32_t bk_col = (g & 1) * 4;

    #pragma unroll
    for (int it = 0; it < 8; it++) {
        int idx = tid + it * 128;
        int r = idx >> 4, c4 = (idx & 15) * 4;
        float4 v = *reinterpret_cast<const float4*>(
            Qp + (size_t)(b * S_ + q0 + r) * q_stride + h * HD_ + c4);
        uint32_t* d = &Qs[r * AT_PAD + c4];
        d[0] = f2tf32(v.x); d[1] = f2tf32(v.y);
        d[2] = f2tf32(v.z); d[3] = f2tf32(v.w);
    }
    __syncthreads();
    uint32_t qf[8][4];
    #pragma unroll
    for (int k8 = 0; k8 < 8; k8++)
        ldsm_x4(aq_off + k8 * 8 * 4, qf[k8][0], qf[k8][1], qf[k8][2], qf[k8][3]);

    float oacc[8][4];
    #pragma unroll
    for (int nt = 0; nt < 8; nt++)
        #pragma unroll
        for (int u = 0; u < 4; u++) oacc[nt][u] = 0.f;
    float m_i[2] = {-1e30f, -1e30f};
    float l_i[2] = {0.f, 0.f};

    int row_r = lane >> 2;
    int cq    = (lane & 3) * 2;
    int ktiles = CAUSAL ? (q0 / 64 + 1) : (kv_len / 64);
    const float* mrow = maskp ? (maskp + (size_t)b * kv_len) : nullptr;

    for (int kt = 0; kt < ktiles; kt++) {
        int k0 = kt * 64;
        __syncthreads();
        #pragma unroll
        for (int it = 0; it < 8; it++) {
            int idx = tid + it * 128;
            int r = idx >> 4, c4 = (idx & 15) * 4;
            size_t off = (size_t)(b * kv_len + k0 + r) * kv_stride + h * HD_ + c4;
            float4 kv = *reinterpret_cast<const float4*>(Kp + off);
            uint32_t* d = &Ks[r * AT_PAD + c4];
            d[0] = f2tf32(kv.x); d[1] = f2tf32(kv.y);
            d[2] = f2tf32(kv.z); d[3] = f2tf32(kv.w);
            float4 vv = *reinterpret_cast<const float4*>(Vp + off);
            Vt[(c4 + 0) * AT_PAD + r] = f2tf32(vv.x);
            Vt[(c4 + 1) * AT_PAD + r] = f2tf32(vv.y);
            Vt[(c4 + 2) * AT_PAD + r] = f2tf32(vv.z);
            Vt[(c4 + 3) * AT_PAD + r] = f2tf32(vv.w);
        }
        __syncthreads();

        float sacc[8][4];
        #pragma unroll
        for (int nt = 0; nt < 8; nt++)
            #pragma unroll
            for (int u = 0; u < 4; u++) sacc[nt][u] = 0.f;
        #pragma unroll
        for (int k8 = 0; k8 < 8; k8++) {
            uint32_t bfr[8][2];
            #pragma unroll
            for (int np = 0; np < 4; np++) {
                uint32_t r0, r1, r2, r3;
                ldsm_x4(ks_base + ((np * 16 + bk_row) * AT_PAD + bk_col + k8 * 8) * 4,
                        r0, r1, r2, r3);
                bfr[np * 2 + 0][0] = r0; bfr[np * 2 + 0][1] = r1;
                bfr[np * 2 + 1][0] = r2; bfr[np * 2 + 1][1] = r3;
            }
            #pragma unroll
            for (int nt = 0; nt < 8; nt++)
                mma_tf32(sacc[nt][0], sacc[nt][1], sacc[nt][2], sacc[nt][3],
                         qf[k8][0], qf[k8][1], qf[k8][2], qf[k8][3],
                         bfr[nt][0], bfr[nt][1]);
        }

        float mv[8][2];
        #pragma unroll
        for (int nt = 0; nt < 8; nt++) {
            mv[nt][0] = mrow ? mrow[k0 + nt * 8 + cq]     : 0.f;
            mv[nt][1] = mrow ? mrow[k0 + nt * 8 + cq + 1] : 0.f;
        }
        #pragma unroll
        for (int nt = 0; nt < 8; nt++)
            #pragma unroll
            for (int u = 0; u < 4; u++) {
                int half = u >> 1;
                float v = sacc[nt][u] * 0.125f + mv[nt][u & 1];
                if (CAUSAL && kt == q0 / 64) {
                    int qrow = q0 + w * 16 + row_r + half * 8;
                    int kcol = k0 + nt * 8 + cq + (u & 1);
                    if (kcol > qrow) v = -1e30f;
                }
                sacc[nt][u] = v;
            }

        #pragma unroll
        for (int half = 0; half < 2; half++) {
            float mt = -1e30f;
            #pragma unroll
            for (int nt = 0; nt < 8; nt++)
                mt = fmaxf(mt, fmaxf(sacc[nt][half * 2], sacc[nt][half * 2 + 1]));
            mt = fmaxf(mt, __shfl_xor_sync(0xffffffffu, mt, 1));
            mt = fmaxf(mt, __shfl_xor_sync(0xffffffffu, mt, 2));
            float mn = fmaxf(m_i[half], mt);
            float alpha = __expf(m_i[half] - mn);
            m_i[half] = mn;
            float sum = 0.f;
            int prow = (w * 16 + row_r + half * 8) * AT_PAD;
            #pragma unroll
            for (int nt = 0; nt < 8; nt++) {
                float p0 = __expf(sacc[nt][half * 2 + 0] - mn);
                float p1 = __expf(sacc[nt][half * 2 + 1] - mn);
                sum += p0 + p1;
                Ps[prow + nt * 8 + cq + 0] = f2tf32(p0);
                Ps[prow + nt * 8 + cq + 1] = f2tf32(p1);
            }
            sum += __shfl_xor_sync(0xffffffffu, sum, 1);
            sum += __shfl_xor_sync(0xffffffffu, sum, 2);
            l_i[half] = l_i[half] * alpha + sum;
            #pragma unroll
            for (int nt = 0; nt < 8; nt++) {
                oacc[nt][half * 2 + 0] *= alpha;
                oacc[nt][half * 2 + 1] *= alpha;
            }
        }
        __syncwarp();

        #pragma unroll
        for (int k8 = 0; k8 < 8; k8++) {
            uint32_t pa[4];
            ldsm_x4(ap_off + k8 * 8 * 4, pa[0], pa[1], pa[2], pa[3]);
            uint32_t bfr[8][2];
            #pragma unroll
            for (int np = 0; np < 4; np++) {
                uint32_t r0, r1, r2, r3;
                ldsm_x4(vt_base + ((np * 16 + bk_row) * AT_PAD + bk_col + k8 * 8) * 4,
                        r0, r1, r2, r3);
                bfr[np * 2 + 0][0] = r0; bfr[np * 2 + 0][1] = r1;
                bfr[np * 2 + 1][0] = r2; bfr[np * 2 + 1][1] = r3;
            }
            #pragma unroll
            for (int nt = 0; nt < 8; nt++)
                mma_tf32(oacc[nt][0], oacc[nt][1], oacc[nt][2], oacc[nt][3],
                         pa[0], pa[1], pa[2], pa[3],
                         bfr[nt][0], bfr[nt][1]);
        }
    }

    #pragma unroll
    for (int half = 0; half < 2; half++) {
        int q = q0 + w * 16 + row_r + half * 8;
        float inv = 1.0f / l_i[half];
        #pragma unroll
        for (int nt = 0; nt < 8; nt++) {
            float2 o = make_float2(oacc[nt][half * 2 + 0] * inv,
                                   oacc[nt][half * 2 + 1] * inv);
            *reinterpret_cast<float2*>(
                &Op[(size_t)(b * S_ + q) * H_ + h * HD_ + nt * 8 + cq]) = o;
        }
    }
}

// ---------------- launch ---------------------------------------------------
extern "C" void kernel_launch(void* const* d_in, const int* in_sizes, int n_in,
                              void* d_out, int out_size) {
    const float* x      = (const float*)d_in[0];
    const float* rope   = (const float*)d_in[1];
    const float* cond   = (const float*)d_in[3];
    const float* cmask  = (const float*)d_in[4];
    const float* ln1_g  = (const float*)d_in[5];
    const float* ln1_b  = (const float*)d_in[6];
    const float* ln2_g  = (const float*)d_in[7];
    const float* ln2_b  = (const float*)d_in[8];
    const float* lnc_g  = (const float*)d_in[9];
    const float* lnc_b  = (const float*)d_in[10];
    const float* w_qkv  = (const float*)d_in[11];
    const float* w_out  = (const float*)d_in[12];
    const float* b_out  = (const float*)d_in[13];
    const float* w_cq   = (const float*)d_in[14];
    const float* w_ckv  = (const float*)d_in[15];
    const float* w_cout = (const float*)d_in[16];
    const float* b_cout = (const float*)d_in[17];
    const float* w_ff1  = (const float*)d_in[18];
    const float* b_ff1  = (const float*)d_in[19];
    const float* w_ff2  = (const float*)d_in[20];
    const float* b_ff2  = (const float*)d_in[21];
    float* out = (float*)d_out;

    float *h, *qkv, *attn, *xb, *q2, *kvc, *ff, *rtab;
    cudaGetSymbolAddress((void**)&h,    g_h);
    cudaGetSymbolAddress((void**)&qkv,  g_qkv);
    cudaGetSymbolAddress((void**)&attn, g_attn);
    cudaGetSymbolAddress((void**)&xb,   g_x);
    cudaGetSymbolAddress((void**)&q2,   g_q2);
    cudaGetSymbolAddress((void**)&kvc,  g_kvc);
    cudaGetSymbolAddress((void**)&ff,   g_ff);
    cudaGetSymbolAddress((void**)&rtab, g_rtab);

    cudaFuncSetAttribute(attn_mma_kernel<true>,  cudaFuncAttributeMaxDynamicSharedMemorySize, ATTN_SMEM_BYTES);
    cudaFuncSetAttribute(attn_mma_kernel<false>, cudaFuncAttributeMaxDynamicSharedMemorySize, ATTN_SMEM_BYTES);
    cudaFuncSetAttribute(tgemm_kernel<EPI_NONE>,     cudaFuncAttributeMaxDynamicSharedMemorySize, TG_SMEM_BYTES);
    cudaFuncSetAttribute(tgemm_kernel<EPI_BIAS_RES>, cudaFuncAttributeMaxDynamicSharedMemorySize, TG_SMEM_BYTES);
    cudaFuncSetAttribute(tgemm_kernel<EPI_GELU>,     cudaFuncAttributeMaxDynamicSharedMemorySize, TG_SMEM_BYTES);

    const int rows = ROWS_;

    // --- self attention ---
    rope_table_kernel<<<S_ * 32 / 256, 256>>>(rope, rtab);
    ln_kernel<<<rows, 256>>>(x, ln1_g, ln1_b, h);
    tgemm_kernel<EPI_NONE><<<dim3(3 * H_ / 128, rows / 128), 256, TG_SMEM_BYTES>>>(
        h, w_qkv, nullptr, nullptr, qkv, rows, 3 * H_, H_);
    rope_kernel<<<rows, 256>>>(qkv, rtab);
    attn_mma_kernel<true><<<dim3(S_ / 64, NH_, B_), 128, ATTN_SMEM_BYTES>>>(
        qkv, 3 * H_, qkv + H_, qkv + 2 * H_, 3 * H_, S_, nullptr, attn);
    tgemm_kernel<EPI_BIAS_RES><<<dim3(H_ / 128, rows / 128), 256, TG_SMEM_BYTES>>>(
        attn, w_out, b_out, x, xb, rows, H_, H_);

    // --- cross attention ---
    ln_kernel<<<rows, 256>>>(xb, lnc_g, lnc_b, h);
    tgemm_kernel<EPI_NONE><<<dim3(H_ / 128, rows / 128), 256, TG_SMEM_BYTES>>>(
        h, w_cq, nullptr, nullptr, q2, rows, H_, H_);
    tgemm_kernel<EPI_NONE><<<dim3(2 * H_ / 128, (B_ * C_) / 128), 256, TG_SMEM_BYTES>>>(
        cond, w_ckv, nullptr, nullptr, kvc, B_ * C_, 2 * H_, H_);
    attn_mma_kernel<false><<<dim3(S_ / 64, NH_, B_), 128, ATTN_SMEM_BYTES>>>(
        q2, H_, kvc, kvc + H_, 2 * H_, C_, cmask, attn);
    tgemm_kernel<EPI_BIAS_RES><<<dim3(H_ / 128, rows / 128), 256, TG_SMEM_BYTES>>>(
        attn, w_cout, b_cout, xb, xb, rows, H_, H_);

    // --- FFN ---
    ln_kernel<<<rows, 256>>>(xb, ln2_g, ln2_b, h);
    tgemm_kernel<EPI_GELU><<<dim3(FF_ / 128, rows / 128), 256, TG_SMEM_BYTES>>>(
        h, w_ff1, b_ff1, nullptr, ff, rows, FF_, H_);
    tgemm_kernel<EPI_BIAS_RES><<<dim3(H_ / 128, rows / 128), 256, TG_SMEM_BYTES>>>(
        ff, w_ff2, b_ff2, xb, out, rows, H_, FF_);
}